// round 1
// baseline (speedup 1.0000x reference)
#include <cuda_runtime.h>
#include <math.h>

#define B_ 4
#define L_ 1024
#define D_ 1024
#define S_ 32
#define R_ 6
#define H_ 256
#define SR_ (S_*R_)       // 192
#define M_ (B_*L_)        // 4096

// ---------------- scratch (device globals; no allocation allowed) ----------------
static __device__ float g_rbp[SR_*4*H_];          // role_bias partials (4 d-chunks)
static __device__ float g_scores[B_*S_*R_*L_];    // scores, then filler_weights in place
static __device__ float g_xm[B_*D_];
static __device__ float g_fit[B_*S_];
static __device__ float g_selh[B_*H_];
static __device__ float g_selw[B_*S_];
static __device__ float g_cw[B_*R_*L_];
static __device__ float g_bw[B_*R_*D_];
static __device__ float g_hid[B_*2*H_];
static __device__ float g_repr[B_*D_];

__device__ __forceinline__ float gelu_f(float v) {
    return 0.5f * v * (1.0f + erff(v * 0.70710678118654752440f));
}
__device__ __forceinline__ float sigmoid_f(float v) {
    return 1.0f / (1.0f + expf(-v));
}

// ---------------- xm = mean over L ----------------
__global__ void k_xm(const float* __restrict__ x) {
    int b = blockIdx.x, dc = blockIdx.y;
    int dl = threadIdx.x & 31, ph = threadIdx.x >> 5;   // 128 threads: 32 d x 4 phases
    int d = dc * 32 + dl;
    float s = 0.f;
    for (int l = ph; l < L_; l += 4)
        s += x[((size_t)b * L_ + l) * D_ + d];
    __shared__ float sm[4][32];
    sm[ph][dl] = s;
    __syncthreads();
    if (ph == 0) {
        float t = sm[0][dl] + sm[1][dl] + sm[2][dl] + sm[3][dl];
        g_xm[b * D_ + d] = t * (1.0f / (float)L_);
    }
}

// ---------------- sel hidden: gelu(xm @ Wsel1 + bsel1) ----------------
__global__ void k_selh(const float* __restrict__ Wsel1, const float* __restrict__ bsel1) {
    int b = blockIdx.x, h = threadIdx.x;   // 256 threads
    __shared__ float xm[D_];
    for (int i = h; i < D_; i += H_) xm[i] = g_xm[b * D_ + i];
    __syncthreads();
    float acc = bsel1[h];
    #pragma unroll 8
    for (int d = 0; d < D_; d++)
        acc = fmaf(xm[d], Wsel1[(size_t)d * H_ + h], acc);
    g_selh[b * H_ + h] = gelu_f(acc);
}

// ---------------- fit heads ----------------
__global__ void k_fit(const float* __restrict__ schema_emb, const float* __restrict__ Wf1,
                      const float* __restrict__ bf1, const float* __restrict__ Wf2,
                      const float* __restrict__ bf2) {
    int b = blockIdx.x, s = blockIdx.y;
    int h = threadIdx.x;                    // 256 threads
    __shared__ float fin[D_];
    for (int i = h; i < D_; i += H_) fin[i] = schema_emb[s * D_ + i] + g_xm[b * D_ + i];
    __syncthreads();
    const float* W = Wf1 + (size_t)s * D_ * H_ + h;
    float acc = bf1[s * H_ + h];
    #pragma unroll 8
    for (int d = 0; d < D_; d++)
        acc = fmaf(fin[d], W[(size_t)d * H_], acc);
    float v = gelu_f(acc) * Wf2[s * H_ + h];
    // block sum (256)
    #pragma unroll
    for (int o = 16; o > 0; o >>= 1) v += __shfl_xor_sync(0xffffffffu, v, o);
    __shared__ float rs[8];
    if ((threadIdx.x & 31) == 0) rs[threadIdx.x >> 5] = v;
    __syncthreads();
    if (threadIdx.x == 0) {
        float t = 0.f;
        #pragma unroll
        for (int w = 0; w < 8; w++) t += rs[w];
        g_fit[b * S_ + s] = sigmoid_f(t + bf2[s]);
    }
}

// ---------------- selection: logits, softmax, argmax; writes 3 outputs ----------------
__global__ void k_sel2(const float* __restrict__ Wsel2, const float* __restrict__ bsel2,
                       float* __restrict__ out_fit, float* __restrict__ out_selw,
                       float* __restrict__ out_best) {
    int b = blockIdx.x, s = threadIdx.x;    // 32 threads
    float acc = bsel2[s];
    #pragma unroll 8
    for (int h = 0; h < H_; h++)
        acc = fmaf(g_selh[b * H_ + h], Wsel2[h * S_ + s], acc);
    float fit = g_fit[b * S_ + s];
    float logit = acc + fit;
    float m = logit;
    #pragma unroll
    for (int o = 16; o > 0; o >>= 1) m = fmaxf(m, __shfl_xor_sync(0xffffffffu, m, o));
    float e = expf(logit - m);
    float sum = e;
    #pragma unroll
    for (int o = 16; o > 0; o >>= 1) sum += __shfl_xor_sync(0xffffffffu, sum, o);
    float w = e / sum;
    g_selw[b * S_ + s] = w;
    out_selw[b * S_ + s] = w;
    out_fit[b * S_ + s] = fit;
    float mw = w;
    #pragma unroll
    for (int o = 16; o > 0; o >>= 1) mw = fmaxf(mw, __shfl_xor_sync(0xffffffffu, mw, o));
    unsigned mask = __ballot_sync(0xffffffffu, w == mw);
    if (s == 0) out_best[b] = (float)(__ffs(mask) - 1);
}

// ---------------- role_bias partials: role_emb @ Wr1r ----------------
__global__ void k_rbp(const float* __restrict__ role_emb, const float* __restrict__ Wr1r) {
    int sr = blockIdx.x, c = blockIdx.y;    // 192 x 4, 256 threads
    int h = threadIdx.x;
    __shared__ float re[256];
    re[h] = role_emb[sr * D_ + c * 256 + h];
    __syncthreads();
    const float* W = Wr1r + ((size_t)sr * D_ + c * 256) * H_ + h;
    float acc = 0.f;
    #pragma unroll 8
    for (int d = 0; d < 256; d++)
        acc = fmaf(re[d], W[(size_t)d * H_], acc);
    g_rbp[(sr * 4 + c) * H_ + h] = acc;
}

// ---------------- THE BIG FUSED KERNEL ----------------
// scores[b,s,r,l] = sigmoid( sum_h gelu( x[b,l,:]·Wr1x[s,r,:,h] + rb[s,r,h] ) * Wr2[s,r,h] + br2[s,r] )
#define MT 64
#define KT 16
__global__ __launch_bounds__(256) void k_big(const float* __restrict__ x,
                                             const float* __restrict__ Wr1x,
                                             const float* __restrict__ Wr2,
                                             const float* __restrict__ br2,
                                             const float* __restrict__ br1) {
    __shared__ float xs[KT][MT];
    __shared__ float ws[KT][H_];
    __shared__ float rbs[H_];
    __shared__ float w2s[H_];
    __shared__ float sred[8][64];

    int tid = threadIdx.x;
    int mtile = blockIdx.x;          // 0..63
    int sr = blockIdx.y;             // 0..191
    const float* W = Wr1x + (size_t)sr * D_ * H_;

    rbs[tid] = br1[sr * H_ + tid]
             + g_rbp[(sr * 4 + 0) * H_ + tid] + g_rbp[(sr * 4 + 1) * H_ + tid]
             + g_rbp[(sr * 4 + 2) * H_ + tid] + g_rbp[(sr * 4 + 3) * H_ + tid];
    w2s[tid] = Wr2[sr * H_ + tid];

    int rg = tid & 7;                // 8 row-groups of 8 rows
    int cg = tid >> 3;               // 32 col-groups of 8 cols
    int row0 = mtile * MT;

    float acc[8][8];
    #pragma unroll
    for (int i = 0; i < 8; i++)
        #pragma unroll
        for (int j = 0; j < 8; j++) acc[i][j] = 0.f;

    int lr = tid >> 2;               // row within tile for x loads
    int kq = (tid & 3) * 4;
    const float* xrow = x + (size_t)(row0 + lr) * D_ + kq;

    for (int k0 = 0; k0 < D_; k0 += KT) {
        __syncthreads();
        {   // x tile -> transposed smem
            float4 v = *(const float4*)(xrow + k0);
            xs[kq + 0][lr] = v.x; xs[kq + 1][lr] = v.y;
            xs[kq + 2][lr] = v.z; xs[kq + 3][lr] = v.w;
        }
        #pragma unroll
        for (int j = 0; j < 4; j++) {      // W tile: 16x256 = 1024 float4 slots
            int slot = tid + j * 256;
            int d = slot >> 6, h4 = slot & 63;
            *(float4*)&ws[d][h4 * 4] = *(const float4*)(W + (size_t)(k0 + d) * H_ + h4 * 4);
        }
        __syncthreads();
        #pragma unroll
        for (int k = 0; k < KT; k++) {
            float4 a0 = *(const float4*)&xs[k][rg * 8];
            float4 a1 = *(const float4*)&xs[k][rg * 8 + 4];
            float4 b0 = *(const float4*)&ws[k][cg * 8];
            float4 b1 = *(const float4*)&ws[k][cg * 8 + 4];
            float a[8] = {a0.x, a0.y, a0.z, a0.w, a1.x, a1.y, a1.z, a1.w};
            float bb[8] = {b0.x, b0.y, b0.z, b0.w, b1.x, b1.y, b1.z, b1.w};
            #pragma unroll
            for (int i = 0; i < 8; i++)
                #pragma unroll
                for (int j = 0; j < 8; j++)
                    acc[i][j] = fmaf(a[i], bb[j], acc[i][j]);
        }
    }

    // epilogue: gelu, dot with Wr2, reduce over the 32 col-groups
    float part[8];
    #pragma unroll
    for (int i = 0; i < 8; i++) {
        float p = 0.f;
        #pragma unroll
        for (int j = 0; j < 8; j++) {
            int h = cg * 8 + j;
            float v = acc[i][j] + rbs[h];
            p = fmaf(gelu_f(v), w2s[h], p);
        }
        p += __shfl_down_sync(0xffffffffu, p, 8);
        p += __shfl_down_sync(0xffffffffu, p, 16);
        part[i] = p;
    }
    int warp = tid >> 5;
    if ((tid & 31) < 8) {
        #pragma unroll
        for (int i = 0; i < 8; i++)
            sred[warp][(tid & 7) * 8 + i] = part[i];
    }
    __syncthreads();
    if (tid < 64) {
        float s = 0.f;
        #pragma unroll
        for (int w = 0; w < 8; w++) s += sred[w][tid];
        int grow = row0 + tid;
        int b = grow >> 10, l = grow & 1023;
        int sch = sr / R_, rr = sr % R_;
        float val = sigmoid_f(s + br2[sr]);
        g_scores[((size_t)(b * S_ + sch) * R_ + rr) * L_ + l] = val;
    }
}

// ---------------- iterative binding refinement + filler softmax (in place) ----------------
__device__ __forceinline__ void breduce6(float* v, float (*sm)[8], int is_sum) {
    int lane = threadIdx.x & 31, w = threadIdx.x >> 5;
    #pragma unroll
    for (int r = 0; r < 6; r++) {
        float t = v[r];
        #pragma unroll
        for (int o = 16; o > 0; o >>= 1) {
            float u = __shfl_xor_sync(0xffffffffu, t, o);
            t = is_sum ? (t + u) : fmaxf(t, u);
        }
        if (lane == 0) sm[r][w] = t;
    }
    __syncthreads();
    #pragma unroll
    for (int r = 0; r < 6; r++) {
        float t = sm[r][0];
        #pragma unroll
        for (int w2 = 1; w2 < 8; w2++) t = is_sum ? (t + sm[r][w2]) : fmaxf(t, sm[r][w2]);
        v[r] = t;
    }
    __syncthreads();
}

__global__ __launch_bounds__(256) void k_refine() {
    int b = blockIdx.x, s = blockIdx.y;
    size_t base = (size_t)(b * S_ + s) * R_ * L_;
    int l0 = threadIdx.x;
    __shared__ float red[6][8];
    float sc[6][4];
    #pragma unroll
    for (int r = 0; r < 6; r++)
        #pragma unroll
        for (int j = 0; j < 4; j++)
            sc[r][j] = g_scores[base + r * L_ + l0 + j * 256];

    const float inv = 0.03125f;  // 1/sqrt(1024)
    for (int it = 0; it < 3; it++) {
        float rp[6][4];
        #pragma unroll
        for (int j = 0; j < 4; j++) {
            float m = sc[0][j];
            #pragma unroll
            for (int r = 1; r < 6; r++) m = fmaxf(m, sc[r][j]);
            float sum = 0.f;
            #pragma unroll
            for (int r = 0; r < 6; r++) { rp[r][j] = expf(sc[r][j] - m); sum += rp[r][j]; }
            float isum = 1.f / sum;
            #pragma unroll
            for (int r = 0; r < 6; r++) rp[r][j] *= isum;
        }
        float mx[6];
        #pragma unroll
        for (int r = 0; r < 6; r++) {
            mx[r] = sc[r][0];
            #pragma unroll
            for (int j = 1; j < 4; j++) mx[r] = fmaxf(mx[r], sc[r][j]);
        }
        breduce6(mx, red, 0);
        float tp[6][4], sums[6];
        #pragma unroll
        for (int r = 0; r < 6; r++) {
            sums[r] = 0.f;
            #pragma unroll
            for (int j = 0; j < 4; j++) { tp[r][j] = expf((sc[r][j] - mx[r]) * inv); sums[r] += tp[r][j]; }
        }
        breduce6(sums, red, 1);
        #pragma unroll
        for (int r = 0; r < 6; r++) {
            float isum = 1.f / sums[r];
            #pragma unroll
            for (int j = 0; j < 4; j++)
                sc[r][j] = rp[r][j] * (tp[r][j] * isum) * sc[r][j];
        }
    }
    // final filler softmax over l
    float mx[6];
    #pragma unroll
    for (int r = 0; r < 6; r++) {
        mx[r] = sc[r][0];
        #pragma unroll
        for (int j = 1; j < 4; j++) mx[r] = fmaxf(mx[r], sc[r][j]);
    }
    breduce6(mx, red, 0);
    float e[6][4], sums[6];
    #pragma unroll
    for (int r = 0; r < 6; r++) {
        sums[r] = 0.f;
        #pragma unroll
        for (int j = 0; j < 4; j++) { e[r][j] = expf(sc[r][j] - mx[r]); sums[r] += e[r][j]; }
    }
    breduce6(sums, red, 1);
    #pragma unroll
    for (int r = 0; r < 6; r++) {
        float isum = 1.f / sums[r];
        #pragma unroll
        for (int j = 0; j < 4; j++)
            g_scores[base + r * L_ + l0 + j * 256] = e[r][j] * isum;
    }
}

// ---------------- cw[b,r,l] = sum_s selw[b,s] * fw[b,s,r,l] ----------------
__global__ void k_cw() {
    int idx = blockIdx.x * 256 + threadIdx.x;    // B*R*L = 24576
    int b = idx / (R_ * L_);
    int rl = idx % (R_ * L_);
    int r = rl / L_, l = rl % L_;
    float acc = 0.f;
    #pragma unroll 8
    for (int s = 0; s < S_; s++)
        acc = fmaf(g_selw[b * S_ + s], g_scores[((size_t)(b * S_ + s) * R_ + r) * L_ + l], acc);
    g_cw[idx] = acc;
}

// ---------------- bound_weighted[b,r,d] = sum_l cw[b,r,l] * x[b,l,d] ----------------
__global__ __launch_bounds__(256) void k_bw(const float* __restrict__ x, float* __restrict__ out_bw) {
    int b = blockIdx.x, dblk = blockIdx.y;       // (4, 16)
    int dl = threadIdx.x & 63, ph = threadIdx.x >> 6;
    int d = dblk * 64 + dl;
    __shared__ float cw[R_ * L_];                // 24KB
    for (int i = threadIdx.x; i < R_ * L_; i += 256) cw[i] = g_cw[b * R_ * L_ + i];
    __syncthreads();
    float acc[6] = {0.f, 0.f, 0.f, 0.f, 0.f, 0.f};
    for (int l = ph * 256; l < ph * 256 + 256; l++) {
        float xv = x[((size_t)b * L_ + l) * D_ + d];
        #pragma unroll
        for (int r = 0; r < 6; r++) acc[r] = fmaf(cw[r * L_ + l], xv, acc[r]);
    }
    __shared__ float red[6][4][64];
    #pragma unroll
    for (int r = 0; r < 6; r++) red[r][ph][dl] = acc[r];
    __syncthreads();
    if (ph == 0) {
        #pragma unroll
        for (int r = 0; r < 6; r++) {
            float t = red[r][0][dl] + red[r][1][dl] + red[r][2][dl] + red[r][3][dl];
            g_bw[(b * R_ + r) * D_ + d] = t;
            out_bw[(b * R_ + r) * D_ + d] = t;
        }
    }
}

// ---------------- projection MLP ----------------
__global__ void k_p1(const float* __restrict__ Wp1, const float* __restrict__ bp1) {
    int b = blockIdx.x;
    int j = blockIdx.y * 256 + threadIdx.x;      // 512 cols
    __shared__ float bf[R_ * D_];                // 24KB
    for (int i = threadIdx.x; i < R_ * D_; i += 256) bf[i] = g_bw[b * R_ * D_ + i];
    __syncthreads();
    float acc = bp1[j];
    #pragma unroll 8
    for (int i = 0; i < R_ * D_; i++)
        acc = fmaf(bf[i], Wp1[(size_t)i * (2 * H_) + j], acc);
    g_hid[b * (2 * H_) + j] = gelu_f(acc);
}

__global__ void k_p2(const float* __restrict__ Wp2, const float* __restrict__ bp2) {
    int b = blockIdx.x;
    __shared__ float hd[2 * H_];
    for (int i = threadIdx.x; i < 2 * H_; i += 256) hd[i] = g_hid[b * (2 * H_) + i];
    __syncthreads();
    #pragma unroll
    for (int dd = 0; dd < 4; dd++) {
        int d = dd * 256 + threadIdx.x;
        float acc = bp2[d];
        #pragma unroll 8
        for (int j = 0; j < 2 * H_; j++)
            acc = fmaf(hd[j], Wp2[(size_t)j * D_ + d], acc);
        g_repr[b * D_ + d] = acc;
    }
}

// ---------------- final residual + RMSNorm ----------------
__global__ __launch_bounds__(256) void k_final(const float* __restrict__ x,
                                               const float* __restrict__ norm_w,
                                               float* __restrict__ out_xs) {
    int row = blockIdx.x;                        // 4096 = b*L + l
    int b = row >> 10;
    const float4* xr = (const float4*)(x + (size_t)row * D_);
    const float4* rp = (const float4*)(g_repr + (size_t)b * D_);
    const float4* nw = (const float4*)norm_w;
    float4 v = xr[threadIdx.x];
    float4 r = rp[threadIdx.x];
    v.x = fmaf(0.1f, r.x, v.x); v.y = fmaf(0.1f, r.y, v.y);
    v.z = fmaf(0.1f, r.z, v.z); v.w = fmaf(0.1f, r.w, v.w);
    float ss = v.x * v.x + v.y * v.y + v.z * v.z + v.w * v.w;
    #pragma unroll
    for (int o = 16; o > 0; o >>= 1) ss += __shfl_xor_sync(0xffffffffu, ss, o);
    __shared__ float rs[8];
    if ((threadIdx.x & 31) == 0) rs[threadIdx.x >> 5] = ss;
    __syncthreads();
    float tot = rs[0] + rs[1] + rs[2] + rs[3] + rs[4] + rs[5] + rs[6] + rs[7];
    float scale = rsqrtf(tot * (1.0f / (float)D_) + 1e-6f);
    float4 w = nw[threadIdx.x];
    float4 o;
    o.x = v.x * scale * w.x; o.y = v.y * scale * w.y;
    o.z = v.z * scale * w.z; o.w = v.w * scale * w.w;
    ((float4*)out_xs)[(size_t)row * 256 + threadIdx.x] = o;
}

// ---------------- launch ----------------
extern "C" void kernel_launch(void* const* d_in, const int* in_sizes, int n_in,
                              void* d_out, int out_size) {
    const float* x          = (const float*)d_in[0];
    const float* role_emb   = (const float*)d_in[1];
    const float* Wr1x       = (const float*)d_in[2];
    const float* Wr1r       = (const float*)d_in[3];
    const float* br1        = (const float*)d_in[4];
    const float* Wr2        = (const float*)d_in[5];
    const float* br2        = (const float*)d_in[6];
    const float* schema_emb = (const float*)d_in[7];
    const float* Wf1        = (const float*)d_in[8];
    const float* bf1        = (const float*)d_in[9];
    const float* Wf2        = (const float*)d_in[10];
    const float* bf2        = (const float*)d_in[11];
    const float* Wp1        = (const float*)d_in[12];
    const float* bp1        = (const float*)d_in[13];
    const float* Wp2        = (const float*)d_in[14];
    const float* bp2        = (const float*)d_in[15];
    const float* Wsel1      = (const float*)d_in[16];
    const float* bsel1      = (const float*)d_in[17];
    const float* Wsel2      = (const float*)d_in[18];
    const float* bsel2      = (const float*)d_in[19];
    const float* norm_w     = (const float*)d_in[20];

    float* out      = (float*)d_out;
    float* out_xs   = out;                               // B*L*D
    float* out_fit  = out + (size_t)B_ * L_ * D_;        // B*S
    float* out_selw = out_fit + B_ * S_;                 // B*S
    float* out_best = out_selw + B_ * S_;                // B
    float* out_bw   = out_best + B_;                     // B*R*D

    k_xm<<<dim3(B_, 32), 128>>>(x);
    k_selh<<<B_, 256>>>(Wsel1, bsel1);
    k_fit<<<dim3(B_, S_), 256>>>(schema_emb, Wf1, bf1, Wf2, bf2);
    k_sel2<<<B_, 32>>>(Wsel2, bsel2, out_fit, out_selw, out_best);
    k_rbp<<<dim3(SR_, 4), 256>>>(role_emb, Wr1r);
    k_big<<<dim3(M_ / MT, SR_), 256>>>(x, Wr1x, Wr2, br2, br1);
    k_refine<<<dim3(B_, S_), 256>>>();
    k_cw<<<(B_ * R_ * L_) / 256, 256>>>();
    k_bw<<<dim3(B_, 16), 256>>>(x, out_bw);
    k_p1<<<dim3(B_, 2), 256>>>(Wp1, bp1);
    k_p2<<<B_, 256>>>(Wp2, bp2);
    k_final<<<M_, 256>>>(x, norm_w, out_xs);
}

// round 3
// speedup vs baseline: 4.3486x; 4.3486x over previous
#include <cuda_runtime.h>
#include <cuda_bf16.h>
#include <cstdint>
#include <math.h>

#define B_ 4
#define L_ 1024
#define D_ 1024
#define S_ 32
#define R_ 6
#define H_ 256
#define SR_ (S_*R_)       // 192
#define M_ (B_*L_)        // 4096
#define SCORE_TOT (B_*S_*R_*L_)

// ---------------- scratch (device globals; no allocation allowed) ----------------
static __device__ float g_rbp[SR_*4*H_];
static __device__ float g_scores[SCORE_TOT];
static __device__ float g_part[2*SCORE_TOT];
static __device__ float g_xm[B_*D_];
static __device__ float g_fit[B_*S_];
static __device__ float g_selh[B_*H_];
static __device__ float g_selw[B_*S_];
static __device__ float g_cw[B_*R_*L_];
static __device__ float g_bw[B_*R_*D_];
static __device__ float g_hid[B_*2*H_];
static __device__ float g_repr[B_*D_];
static __device__ __align__(256) __nv_bfloat16 g_xbf[M_*D_];              // 8 MB
static __device__ __align__(256) __nv_bfloat16 g_wbf[(size_t)SR_*H_*D_];  // 100 MB [sr][h][d]

__device__ __forceinline__ float gelu_f(float v) {
    return 0.5f * v * (1.0f + erff(v * 0.70710678118654752440f));
}
__device__ __forceinline__ float sigmoid_f(float v) {
    return 1.0f / (1.0f + expf(-v));
}

// ---------------- sm_80-era primitives (legal on compute_103 base target) --------
__device__ __forceinline__ uint32_t smem_u32(const void* p) {
    uint32_t a;
    asm("{ .reg .u64 t; cvta.to.shared.u64 t, %1; cvt.u32.u64 %0, t; }" : "=r"(a) : "l"(p));
    return a;
}
__device__ __forceinline__ void cpa16(uint32_t dst, const void* src) {
    asm volatile("cp.async.cg.shared.global [%0], [%1], 16;" :: "r"(dst), "l"(src));
}
#define CP_COMMIT() asm volatile("cp.async.commit_group;" ::: "memory")
#define CP_WAIT(n)  asm volatile("cp.async.wait_group %0;" :: "n"(n) : "memory")

__device__ __forceinline__ void ldm_x4(uint32_t* r, uint32_t addr) {
    asm volatile("ldmatrix.sync.aligned.m8n8.x4.shared.b16 {%0,%1,%2,%3}, [%4];"
        : "=r"(r[0]), "=r"(r[1]), "=r"(r[2]), "=r"(r[3]) : "r"(addr));
}
__device__ __forceinline__ void mma16816(float* d, const uint32_t* a, uint32_t b0, uint32_t b1) {
    asm volatile("mma.sync.aligned.m16n8k16.row.col.f32.bf16.bf16.f32 "
        "{%0,%1,%2,%3}, {%4,%5,%6,%7}, {%8,%9}, {%0,%1,%2,%3};"
        : "+f"(d[0]), "+f"(d[1]), "+f"(d[2]), "+f"(d[3])
        : "r"(a[0]), "r"(a[1]), "r"(a[2]), "r"(a[3]), "r"(b0), "r"(b1));
}

// ---------------- bf16 conversions ----------------
__global__ void k_cvt_x(const float* __restrict__ x) {
    int i = (blockIdx.x * 256 + threadIdx.x) * 4;
    float4 v = *(const float4*)(x + i);
    __nv_bfloat16* o = g_xbf + i;
    o[0] = __float2bfloat16(v.x); o[1] = __float2bfloat16(v.y);
    o[2] = __float2bfloat16(v.z); o[3] = __float2bfloat16(v.w);
}

// Wr1x [sr][d][h] fp32 -> g_wbf [sr][h][d] bf16 (32x32 tile transpose)
__global__ __launch_bounds__(256) void k_cvt_w(const float* __restrict__ W) {
    __shared__ float t[32][33];
    int sr = blockIdx.x, db = blockIdx.y, hb = blockIdx.z;   // (192, 32, 8)
    int tx = threadIdx.x & 31, ty = threadIdx.x >> 5;
    const float* Wp = W + ((size_t)sr * D_ + db * 32) * H_ + hb * 32;
    #pragma unroll
    for (int i = ty; i < 32; i += 8)
        t[i][tx] = Wp[(size_t)i * H_ + tx];
    __syncthreads();
    __nv_bfloat16* Op = g_wbf + ((size_t)sr * H_ + hb * 32) * D_ + db * 32;
    #pragma unroll
    for (int i = ty; i < 32; i += 8)
        Op[(size_t)i * D_ + tx] = __float2bfloat16(t[tx][i]);
}

// ---------------- xm = mean over L ----------------
__global__ void k_xm(const float* __restrict__ x) {
    int b = blockIdx.x, dc = blockIdx.y;
    int dl = threadIdx.x & 31, ph = threadIdx.x >> 5;
    int d = dc * 32 + dl;
    float s = 0.f;
    for (int l = ph; l < L_; l += 4)
        s += x[((size_t)b * L_ + l) * D_ + d];
    __shared__ float sm[4][32];
    sm[ph][dl] = s;
    __syncthreads();
    if (ph == 0) {
        float t = sm[0][dl] + sm[1][dl] + sm[2][dl] + sm[3][dl];
        g_xm[b * D_ + d] = t * (1.0f / (float)L_);
    }
}

// ---------------- sel hidden ----------------
__global__ void k_selh(const float* __restrict__ Wsel1, const float* __restrict__ bsel1) {
    int b = blockIdx.x, h = threadIdx.x;
    __shared__ float xm[D_];
    for (int i = h; i < D_; i += H_) xm[i] = g_xm[b * D_ + i];
    __syncthreads();
    float acc = bsel1[h];
    #pragma unroll 8
    for (int d = 0; d < D_; d++)
        acc = fmaf(xm[d], Wsel1[(size_t)d * H_ + h], acc);
    g_selh[b * H_ + h] = gelu_f(acc);
}

// ---------------- fit heads ----------------
__global__ void k_fit(const float* __restrict__ schema_emb, const float* __restrict__ Wf1,
                      const float* __restrict__ bf1, const float* __restrict__ Wf2,
                      const float* __restrict__ bf2) {
    int b = blockIdx.x, s = blockIdx.y;
    int h = threadIdx.x;
    __shared__ float fin[D_];
    for (int i = h; i < D_; i += H_) fin[i] = schema_emb[s * D_ + i] + g_xm[b * D_ + i];
    __syncthreads();
    const float* W = Wf1 + (size_t)s * D_ * H_ + h;
    float acc = bf1[s * H_ + h];
    #pragma unroll 8
    for (int d = 0; d < D_; d++)
        acc = fmaf(fin[d], W[(size_t)d * H_], acc);
    float v = gelu_f(acc) * Wf2[s * H_ + h];
    #pragma unroll
    for (int o = 16; o > 0; o >>= 1) v += __shfl_xor_sync(0xffffffffu, v, o);
    __shared__ float rs[8];
    if ((threadIdx.x & 31) == 0) rs[threadIdx.x >> 5] = v;
    __syncthreads();
    if (threadIdx.x == 0) {
        float t = 0.f;
        #pragma unroll
        for (int w = 0; w < 8; w++) t += rs[w];
        g_fit[b * S_ + s] = sigmoid_f(t + bf2[s]);
    }
}

// ---------------- selection ----------------
__global__ void k_sel2(const float* __restrict__ Wsel2, const float* __restrict__ bsel2,
                       float* __restrict__ out_fit, float* __restrict__ out_selw,
                       float* __restrict__ out_best) {
    int b = blockIdx.x, s = threadIdx.x;
    float acc = bsel2[s];
    #pragma unroll 8
    for (int h = 0; h < H_; h++)
        acc = fmaf(g_selh[b * H_ + h], Wsel2[h * S_ + s], acc);
    float fit = g_fit[b * S_ + s];
    float logit = acc + fit;
    float m = logit;
    #pragma unroll
    for (int o = 16; o > 0; o >>= 1) m = fmaxf(m, __shfl_xor_sync(0xffffffffu, m, o));
    float e = expf(logit - m);
    float sum = e;
    #pragma unroll
    for (int o = 16; o > 0; o >>= 1) sum += __shfl_xor_sync(0xffffffffu, sum, o);
    float w = e / sum;
    g_selw[b * S_ + s] = w;
    out_selw[b * S_ + s] = w;
    out_fit[b * S_ + s] = fit;
    float mw = w;
    #pragma unroll
    for (int o = 16; o > 0; o >>= 1) mw = fmaxf(mw, __shfl_xor_sync(0xffffffffu, mw, o));
    unsigned mask = __ballot_sync(0xffffffffu, w == mw);
    if (s == 0) out_best[b] = (float)(__ffs(mask) - 1);
}

// ---------------- role_bias partials ----------------
__global__ void k_rbp(const float* __restrict__ role_emb, const float* __restrict__ Wr1r) {
    int sr = blockIdx.x, c = blockIdx.y;
    int h = threadIdx.x;
    __shared__ float re[256];
    re[h] = role_emb[sr * D_ + c * 256 + h];
    __syncthreads();
    const float* W = Wr1r + ((size_t)sr * D_ + c * 256) * H_ + h;
    float acc = 0.f;
    #pragma unroll 8
    for (int d = 0; d < 256; d++)
        acc = fmaf(re[d], W[(size_t)d * H_], acc);
    g_rbp[(sr * 4 + c) * H_ + h] = acc;
}

// ---------------- THE BIG KERNEL: mma.sync bf16 GEMM + fused epilogue ----------------
// CTA: M=128 tokens x N=128 H-half. 8 warps (2 m-rows x 4 n-cols), warp tile 64x32.
// K pipelined: 16 chunks of 64, 3 smem stages via cp.async.
// SW128 swizzled smem unit layout: byte_off(row, c) = (row*8 + (c ^ (row&7))) * 16
#define STG     32768              // 16KB A + 16KB B per stage
#define RBS_OFF (3*STG)
#define W2_OFF  (RBS_OFF + 512)
#define RED_OFF (RBS_OFF + 1024)
#define SMTOT   (RBS_OFF + 1024 + 2048)

__global__ __launch_bounds__(256, 2) void k_big(const float* __restrict__ Wr2,
                                                const float* __restrict__ br1) {
    extern __shared__ char smem[];
    uint32_t sb = smem_u32(smem);
    int tid = threadIdx.x;
    int lane = tid & 31, wid = tid >> 5;
    int wr = wid >> 2, wc = wid & 3;        // warp grid 2x4
    int mtile = blockIdx.x;                 // 0..31
    int nh = blockIdx.y;                    // 0..1
    int sr = blockIdx.z;                    // 0..191

    const __nv_bfloat16* Ag = g_xbf + (size_t)mtile * 128 * D_;
    const __nv_bfloat16* Bg = g_wbf + ((size_t)sr * H_ + nh * 128) * D_;

    float* rbs = (float*)(smem + RBS_OFF);
    float* w2s = (float*)(smem + W2_OFF);
    float* red = (float*)(smem + RED_OFF);
    if (tid < 128) {
        int hg = nh * 128 + tid;
        rbs[tid] = br1[sr * H_ + hg]
                 + g_rbp[(sr * 4 + 0) * H_ + hg] + g_rbp[(sr * 4 + 1) * H_ + hg]
                 + g_rbp[(sr * 4 + 2) * H_ + hg] + g_rbp[(sr * 4 + 3) * H_ + hg];
        w2s[tid] = Wr2[sr * H_ + hg];
    }

    // prologue: issue stages 0..2
    #pragma unroll
    for (int st = 0; st < 3; st++) {
        uint32_t As = sb + st * STG, Bs = As + 16384;
        #pragma unroll
        for (int i = 0; i < 4; i++) {
            int idx = i * 256 + tid;
            int r = idx >> 3, c = idx & 7;
            uint32_t off = (uint32_t)(r * 8 + (c ^ (r & 7))) * 16;
            cpa16(As + off, Ag + (size_t)r * D_ + st * 64 + c * 8);
            cpa16(Bs + off, Bg + (size_t)r * D_ + st * 64 + c * 8);
        }
        CP_COMMIT();
    }

    // per-thread ldmatrix address components
    int g8 = lane >> 3, rr = lane & 7;
    int arow = rr + (g8 & 1) * 8;          // 0..15 within tile
    int coff = g8 >> 1;                    // 0/1 (k-half)

    float acc[4][4][4];
    #pragma unroll
    for (int mt = 0; mt < 4; mt++)
        #pragma unroll
        for (int nt = 0; nt < 4; nt++)
            #pragma unroll
            for (int q = 0; q < 4; q++) acc[mt][nt][q] = 0.f;

    for (int kc = 0; kc < 16; kc++) {
        int rem = 15 - kc;
        if (rem >= 2)      { CP_WAIT(2); }
        else if (rem == 1) { CP_WAIT(1); }
        else               { CP_WAIT(0); }
        __syncthreads();
        int st = kc % 3;
        uint32_t Asb = sb + st * STG, Bsb = Asb + 16384;

        #pragma unroll
        for (int ks = 0; ks < 4; ks++) {
            int c = ks * 2 + coff;
            uint32_t sw = (uint32_t)((c ^ rr) * 16);
            uint32_t a[4][4];
            #pragma unroll
            for (int mt = 0; mt < 4; mt++)
                ldm_x4(a[mt], Asb + (uint32_t)(wr * 64 + mt * 16 + arow) * 128 + sw);
            uint32_t bv[2][4];
            #pragma unroll
            for (int nt2 = 0; nt2 < 2; nt2++)
                ldm_x4(bv[nt2], Bsb + (uint32_t)(wc * 32 + nt2 * 16 + arow) * 128 + sw);
            #pragma unroll
            for (int mt = 0; mt < 4; mt++)
                #pragma unroll
                for (int nt = 0; nt < 4; nt++)
                    mma16816(acc[mt][nt], a[mt], bv[nt >> 1][nt & 1], bv[nt >> 1][(nt & 1) + 2]);
        }
        __syncthreads();
        if (kc + 3 < 16) {
            int knext = kc + 3;
            uint32_t As = sb + st * STG, Bs = As + 16384;
            #pragma unroll
            for (int i = 0; i < 4; i++) {
                int idx = i * 256 + tid;
                int r = idx >> 3, c = idx & 7;
                uint32_t off = (uint32_t)(r * 8 + (c ^ (r & 7))) * 16;
                cpa16(As + off, Ag + (size_t)r * D_ + knext * 64 + c * 8);
                cpa16(Bs + off, Bg + (size_t)r * D_ + knext * 64 + c * 8);
            }
            CP_COMMIT();
        }
    }

    // epilogue: gelu + Wr2-dot + reductions. acc frag: c0=(row l/4, h0), c1=(row, h0+1),
    // c2=(row+8, h0), c3=(row+8, h0+1); h0 = wc*32 + nt*8 + (lane&3)*2
    #pragma unroll
    for (int mt = 0; mt < 4; mt++) {
        float pA = 0.f, pB = 0.f;
        #pragma unroll
        for (int nt = 0; nt < 4; nt++) {
            int h0 = wc * 32 + nt * 8 + (lane & 3) * 2;
            float rb0 = rbs[h0], rb1 = rbs[h0 + 1];
            float w20 = w2s[h0], w21 = w2s[h0 + 1];
            pA = fmaf(gelu_f(acc[mt][nt][0] + rb0), w20, pA);
            pA = fmaf(gelu_f(acc[mt][nt][1] + rb1), w21, pA);
            pB = fmaf(gelu_f(acc[mt][nt][2] + rb0), w20, pB);
            pB = fmaf(gelu_f(acc[mt][nt][3] + rb1), w21, pB);
        }
        pA += __shfl_xor_sync(0xffffffffu, pA, 1);
        pA += __shfl_xor_sync(0xffffffffu, pA, 2);
        pB += __shfl_xor_sync(0xffffffffu, pB, 1);
        pB += __shfl_xor_sync(0xffffffffu, pB, 2);
        if ((lane & 3) == 0) {
            int row = wr * 64 + mt * 16 + (lane >> 2);
            red[wc * 128 + row] = pA;
            red[wc * 128 + row + 8] = pB;
        }
    }
    __syncthreads();
    if (tid < 128) {
        float p = red[tid] + red[128 + tid] + red[256 + tid] + red[384 + tid];
        int grow = mtile * 128 + tid;
        int b = grow >> 10, l = grow & 1023;
        int sch = sr / R_, rrole = sr % R_;
        g_part[(size_t)nh * SCORE_TOT + ((size_t)(b * S_ + sch) * R_ + rrole) * L_ + l] = p;
    }
}

// ---------------- refinement: combine partials + sigmoid, 3 iters, filler softmax ----
__device__ __forceinline__ void breduce6(float* v, float (*sm)[8], int is_sum) {
    int lane = threadIdx.x & 31, w = threadIdx.x >> 5;
    #pragma unroll
    for (int r = 0; r < 6; r++) {
        float t = v[r];
        #pragma unroll
        for (int o = 16; o > 0; o >>= 1) {
            float u = __shfl_xor_sync(0xffffffffu, t, o);
            t = is_sum ? (t + u) : fmaxf(t, u);
        }
        if (lane == 0) sm[r][w] = t;
    }
    __syncthreads();
    #pragma unroll
    for (int r = 0; r < 6; r++) {
        float t = sm[r][0];
        #pragma unroll
        for (int w2 = 1; w2 < 8; w2++) t = is_sum ? (t + sm[r][w2]) : fmaxf(t, sm[r][w2]);
        v[r] = t;
    }
    __syncthreads();
}

__global__ __launch_bounds__(256) void k_refine(const float* __restrict__ br2) {
    int b = blockIdx.x, s = blockIdx.y;
    size_t base = (size_t)(b * S_ + s) * R_ * L_;
    int l0 = threadIdx.x;
    __shared__ float red[6][8];
    float sc[6][4];
    #pragma unroll
    for (int r = 0; r < 6; r++) {
        float bias = br2[s * R_ + r];
        #pragma unroll
        for (int j = 0; j < 4; j++) {
            size_t idx = base + r * L_ + l0 + j * 256;
            sc[r][j] = sigmoid_f(g_part[idx] + g_part[SCORE_TOT + idx] + bias);
        }
    }

    const float inv = 0.03125f;
    for (int it = 0; it < 3; it++) {
        float rp[6][4];
        #pragma unroll
        for (int j = 0; j < 4; j++) {
            float m = sc[0][j];
            #pragma unroll
            for (int r = 1; r < 6; r++) m = fmaxf(m, sc[r][j]);
            float sum = 0.f;
            #pragma unroll
            for (int r = 0; r < 6; r++) { rp[r][j] = expf(sc[r][j] - m); sum += rp[r][j]; }
            float isum = 1.f / sum;
            #pragma unroll
            for (int r = 0; r < 6; r++) rp[r][j] *= isum;
        }
        float mx[6];
        #pragma unroll
        for (int r = 0; r < 6; r++) {
            mx[r] = sc[r][0];
            #pragma unroll
            for (int j = 1; j < 4; j++) mx[r] = fmaxf(mx[r], sc[r][j]);
        }
        breduce6(mx, red, 0);
        float tp[6][4], sums[6];
        #pragma unroll
        for (int r = 0; r < 6; r++) {
            sums[r] = 0.f;
            #pragma unroll
            for (int j = 0; j < 4; j++) { tp[r][j] = expf((sc[r][j] - mx[r]) * inv); sums[r] += tp[r][j]; }
        }
        breduce6(sums, red, 1);
        #pragma unroll
        for (int r = 0; r < 6; r++) {
            float isum = 1.f / sums[r];
            #pragma unroll
            for (int j = 0; j < 4; j++)
                sc[r][j] = rp[r][j] * (tp[r][j] * isum) * sc[r][j];
        }
    }
    float mx[6];
    #pragma unroll
    for (int r = 0; r < 6; r++) {
        mx[r] = sc[r][0];
        #pragma unroll
        for (int j = 1; j < 4; j++) mx[r] = fmaxf(mx[r], sc[r][j]);
    }
    breduce6(mx, red, 0);
    float e[6][4], sums[6];
    #pragma unroll
    for (int r = 0; r < 6; r++) {
        sums[r] = 0.f;
        #pragma unroll
        for (int j = 0; j < 4; j++) { e[r][j] = expf(sc[r][j] - mx[r]); sums[r] += e[r][j]; }
    }
    breduce6(sums, red, 1);
    #pragma unroll
    for (int r = 0; r < 6; r++) {
        float isum = 1.f / sums[r];
        #pragma unroll
        for (int j = 0; j < 4; j++)
            g_scores[base + r * L_ + l0 + j * 256] = e[r][j] * isum;
    }
}

// ---------------- cw[b,r,l] = sum_s selw * fw ----------------
__global__ void k_cw() {
    int idx = blockIdx.x * 256 + threadIdx.x;
    int b = idx / (R_ * L_);
    int rl = idx % (R_ * L_);
    int r = rl / L_, l = rl % L_;
    float acc = 0.f;
    #pragma unroll 8
    for (int s = 0; s < S_; s++)
        acc = fmaf(g_selw[b * S_ + s], g_scores[((size_t)(b * S_ + s) * R_ + r) * L_ + l], acc);
    g_cw[idx] = acc;
}

// ---------------- bound_weighted ----------------
__global__ __launch_bounds__(256) void k_bw(const float* __restrict__ x, float* __restrict__ out_bw) {
    int b = blockIdx.x, dblk = blockIdx.y;
    int dl = threadIdx.x & 63, ph = threadIdx.x >> 6;
    int d = dblk * 64 + dl;
    __shared__ float cw[R_ * L_];
    for (int i = threadIdx.x; i < R_ * L_; i += 256) cw[i] = g_cw[b * R_ * L_ + i];
    __syncthreads();
    float acc[6] = {0.f, 0.f, 0.f, 0.f, 0.f, 0.f};
    for (int l = ph * 256; l < ph * 256 + 256; l++) {
        float xv = x[((size_t)b * L_ + l) * D_ + d];
        #pragma unroll
        for (int r = 0; r < 6; r++) acc[r] = fmaf(cw[r * L_ + l], xv, acc[r]);
    }
    __shared__ float red[6][4][64];
    #pragma unroll
    for (int r = 0; r < 6; r++) red[r][ph][dl] = acc[r];
    __syncthreads();
    if (ph == 0) {
        #pragma unroll
        for (int r = 0; r < 6; r++) {
            float t = red[r][0][dl] + red[r][1][dl] + red[r][2][dl] + red[r][3][dl];
            g_bw[(b * R_ + r) * D_ + d] = t;
            out_bw[(b * R_ + r) * D_ + d] = t;
        }
    }
}

// ---------------- projection MLP ----------------
__global__ void k_p1(const float* __restrict__ Wp1, const float* __restrict__ bp1) {
    int b = blockIdx.x;
    int j = blockIdx.y * 256 + threadIdx.x;
    __shared__ float bf[R_ * D_];
    for (int i = threadIdx.x; i < R_ * D_; i += 256) bf[i] = g_bw[b * R_ * D_ + i];
    __syncthreads();
    float acc = bp1[j];
    #pragma unroll 8
    for (int i = 0; i < R_ * D_; i++)
        acc = fmaf(bf[i], Wp1[(size_t)i * (2 * H_) + j], acc);
    g_hid[b * (2 * H_) + j] = gelu_f(acc);
}

__global__ void k_p2(const float* __restrict__ Wp2, const float* __restrict__ bp2) {
    int b = blockIdx.x;
    __shared__ float hd[2 * H_];
    for (int i = threadIdx.x; i < 2 * H_; i += 256) hd[i] = g_hid[b * (2 * H_) + i];
    __syncthreads();
    #pragma unroll
    for (int dd = 0; dd < 4; dd++) {
        int d = dd * 256 + threadIdx.x;
        float acc = bp2[d];
        #pragma unroll 8
        for (int j = 0; j < 2 * H_; j++)
            acc = fmaf(hd[j], Wp2[(size_t)j * D_ + d], acc);
        g_repr[b * D_ + d] = acc;
    }
}

// ---------------- final residual + RMSNorm ----------------
__global__ __launch_bounds__(256) void k_final(const float* __restrict__ x,
                                               const float* __restrict__ norm_w,
                                               float* __restrict__ out_xs) {
    int row = blockIdx.x;
    int b = row >> 10;
    const float4* xr = (const float4*)(x + (size_t)row * D_);
    const float4* rp = (const float4*)(g_repr + (size_t)b * D_);
    const float4* nw = (const float4*)norm_w;
    float4 v = xr[threadIdx.x];
    float4 r = rp[threadIdx.x];
    v.x = fmaf(0.1f, r.x, v.x); v.y = fmaf(0.1f, r.y, v.y);
    v.z = fmaf(0.1f, r.z, v.z); v.w = fmaf(0.1f, r.w, v.w);
    float ss = v.x * v.x + v.y * v.y + v.z * v.z + v.w * v.w;
    #pragma unroll
    for (int o = 16; o > 0; o >>= 1) ss += __shfl_xor_sync(0xffffffffu, ss, o);
    __shared__ float rs[8];
    if ((threadIdx.x & 31) == 0) rs[threadIdx.x >> 5] = ss;
    __syncthreads();
    float tot = rs[0] + rs[1] + rs[2] + rs[3] + rs[4] + rs[5] + rs[6] + rs[7];
    float scale = rsqrtf(tot * (1.0f / (float)D_) + 1e-6f);
    float4 w = nw[threadIdx.x];
    float4 o;
    o.x = v.x * scale * w.x; o.y = v.y * scale * w.y;
    o.z = v.z * scale * w.z; o.w = v.w * scale * w.w;
    ((float4*)out_xs)[(size_t)row * 256 + threadIdx.x] = o;
}

// ---------------- launch ----------------
extern "C" void kernel_launch(void* const* d_in, const int* in_sizes, int n_in,
                              void* d_out, int out_size) {
    const float* x          = (const float*)d_in[0];
    const float* role_emb   = (const float*)d_in[1];
    const float* Wr1x       = (const float*)d_in[2];
    const float* Wr1r       = (const float*)d_in[3];
    const float* br1        = (const float*)d_in[4];
    const float* Wr2        = (const float*)d_in[5];
    const float* br2        = (const float*)d_in[6];
    const float* schema_emb = (const float*)d_in[7];
    const float* Wf1        = (const float*)d_in[8];
    const float* bf1        = (const float*)d_in[9];
    const float* Wf2        = (const float*)d_in[10];
    const float* bf2        = (const float*)d_in[11];
    const float* Wp1        = (const float*)d_in[12];
    const float* bp1        = (const float*)d_in[13];
    const float* Wp2        = (const float*)d_in[14];
    const float* bp2        = (const float*)d_in[15];
    const float* Wsel1      = (const float*)d_in[16];
    const float* bsel1      = (const float*)d_in[17];
    const float* Wsel2      = (const float*)d_in[18];
    const float* bsel2      = (const float*)d_in[19];
    const float* norm_w     = (const float*)d_in[20];

    float* out      = (float*)d_out;
    float* out_xs   = out;
    float* out_fit  = out + (size_t)B_ * L_ * D_;
    float* out_selw = out_fit + B_ * S_;
    float* out_best = out_selw + B_ * S_;
    float* out_bw   = out_best + B_;

    cudaFuncSetAttribute(k_big, cudaFuncAttributeMaxDynamicSharedMemorySize, SMTOT);

    k_cvt_x<<<M_ * D_ / 1024, 256>>>(x);
    k_cvt_w<<<dim3(SR_, 32, 8), 256>>>(Wr1x);
    k_xm<<<dim3(B_, 32), 128>>>(x);
    k_selh<<<B_, 256>>>(Wsel1, bsel1);
    k_fit<<<dim3(B_, S_), 256>>>(schema_emb, Wf1, bf1, Wf2, bf2);
    k_sel2<<<B_, 32>>>(Wsel2, bsel2, out_fit, out_selw, out_best);
    k_rbp<<<dim3(SR_, 4), 256>>>(role_emb, Wr1r);
    k_big<<<dim3(32, 2, SR_), 256, SMTOT>>>(Wr2, br1);
    k_refine<<<dim3(B_, S_), 256>>>(br2);
    k_cw<<<(B_ * R_ * L_) / 256, 256>>>();
    k_bw<<<dim3(B_, 16), 256>>>(x, out_bw);
    k_p1<<<dim3(B_, 2), 256>>>(Wp1, bp1);
    k_p2<<<B_, 256>>>(Wp2, bp2);
    k_final<<<M_, 256>>>(x, norm_w, out_xs);
}

// round 4
// speedup vs baseline: 4.5673x; 1.0503x over previous
#include <cuda_runtime.h>
#include <cuda_bf16.h>
#include <cstdint>
#include <math.h>

#define B_ 4
#define L_ 1024
#define D_ 1024
#define S_ 32
#define R_ 6
#define H_ 256
#define SR_ (S_*R_)       // 192
#define M_ (B_*L_)        // 4096
#define SCORE_TOT (B_*S_*R_*L_)

// ---------------- scratch (device globals; no allocation allowed) ----------------
static __device__ float g_rbp[SR_*8*H_];
static __device__ float g_scores[SCORE_TOT];
static __device__ float g_part[2*SCORE_TOT];
static __device__ float g_xm[B_*D_];
static __device__ float g_fit[B_*S_];
static __device__ float g_fitp[B_*S_*2*H_];
static __device__ float g_selhp[B_*8*H_];
static __device__ float g_selw[B_*S_];
static __device__ float g_cw[B_*R_*L_];
static __device__ float g_bw[B_*R_*D_];
static __device__ float g_hid[B_*2*H_];
static __device__ float g_repr[B_*D_];
static __device__ __align__(256) __nv_bfloat16 g_xbf[M_*D_];              // 8 MB  [token][d]
static __device__ __align__(256) __nv_bfloat16 g_wbf[(size_t)SR_*D_*H_];  // 100 MB [sr][d][h]

__device__ __forceinline__ float gelu_f(float v) {
    return 0.5f * v * (1.0f + erff(v * 0.70710678118654752440f));
}
__device__ __forceinline__ float sigmoid_f(float v) {
    return 1.0f / (1.0f + expf(-v));
}

// ---------------- sm_80-era primitives (legal on compute_103 base target) --------
__device__ __forceinline__ uint32_t smem_u32(const void* p) {
    uint32_t a;
    asm("{ .reg .u64 t; cvta.to.shared.u64 t, %1; cvt.u32.u64 %0, t; }" : "=r"(a) : "l"(p));
    return a;
}
__device__ __forceinline__ void cpa16(uint32_t dst, const void* src) {
    asm volatile("cp.async.cg.shared.global [%0], [%1], 16;" :: "r"(dst), "l"(src));
}
#define CP_COMMIT() asm volatile("cp.async.commit_group;" ::: "memory")
#define CP_WAIT(n)  asm volatile("cp.async.wait_group %0;" :: "n"(n) : "memory")

__device__ __forceinline__ void ldm_x4(uint32_t* r, uint32_t addr) {
    asm volatile("ldmatrix.sync.aligned.m8n8.x4.shared.b16 {%0,%1,%2,%3}, [%4];"
        : "=r"(r[0]), "=r"(r[1]), "=r"(r[2]), "=r"(r[3]) : "r"(addr));
}
__device__ __forceinline__ void ldm_x4_t(uint32_t* r, uint32_t addr) {
    asm volatile("ldmatrix.sync.aligned.m8n8.x4.trans.shared.b16 {%0,%1,%2,%3}, [%4];"
        : "=r"(r[0]), "=r"(r[1]), "=r"(r[2]), "=r"(r[3]) : "r"(addr));
}
__device__ __forceinline__ void mma16816(float* d, const uint32_t* a, uint32_t b0, uint32_t b1) {
    asm volatile("mma.sync.aligned.m16n8k16.row.col.f32.bf16.bf16.f32 "
        "{%0,%1,%2,%3}, {%4,%5,%6,%7}, {%8,%9}, {%0,%1,%2,%3};"
        : "+f"(d[0]), "+f"(d[1]), "+f"(d[2]), "+f"(d[3])
        : "r"(a[0]), "r"(a[1]), "r"(a[2]), "r"(a[3]), "r"(b0), "r"(b1));
}

// ---------------- bf16 conversions ----------------
__global__ void k_cvt_x(const float* __restrict__ x) {
    int i = (blockIdx.x * 256 + threadIdx.x) * 4;
    float4 v = *(const float4*)(x + i);
    __nv_bfloat16* o = g_xbf + i;
    o[0] = __float2bfloat16(v.x); o[1] = __float2bfloat16(v.y);
    o[2] = __float2bfloat16(v.z); o[3] = __float2bfloat16(v.w);
}

// pure streaming fp32->bf16, layout preserved [sr][d][h]
__global__ void k_cvt_w(const float* __restrict__ W) {
    size_t i = ((size_t)blockIdx.x * 256 + threadIdx.x) * 8;
    float4 v0 = *(const float4*)(W + i);
    float4 v1 = *(const float4*)(W + i + 4);
    __nv_bfloat16* o = g_wbf + i;
    o[0] = __float2bfloat16(v0.x); o[1] = __float2bfloat16(v0.y);
    o[2] = __float2bfloat16(v0.z); o[3] = __float2bfloat16(v0.w);
    o[4] = __float2bfloat16(v1.x); o[5] = __float2bfloat16(v1.y);
    o[6] = __float2bfloat16(v1.z); o[7] = __float2bfloat16(v1.w);
}

// ---------------- xm = mean over L ----------------
__global__ void k_xm(const float* __restrict__ x) {
    int b = blockIdx.x, dc = blockIdx.y;
    int dl = threadIdx.x & 31, ph = threadIdx.x >> 5;
    int d = dc * 32 + dl;
    float s = 0.f;
    for (int l = ph; l < L_; l += 4)
        s += x[((size_t)b * L_ + l) * D_ + d];
    __shared__ float sm[4][32];
    sm[ph][dl] = s;
    __syncthreads();
    if (ph == 0) {
        float t = sm[0][dl] + sm[1][dl] + sm[2][dl] + sm[3][dl];
        g_xm[b * D_ + d] = t * (1.0f / (float)L_);
    }
}

// ---------------- sel hidden partials: (B, 8 d-chunks) ----------------
__global__ void k_selhp(const float* __restrict__ Wsel1) {
    int b = blockIdx.x, c = blockIdx.y;
    int h = threadIdx.x;
    __shared__ float xm[128];
    if (h < 128) xm[h] = g_xm[b * D_ + c * 128 + h];
    __syncthreads();
    const float* W = Wsel1 + (size_t)(c * 128) * H_ + h;
    float acc = 0.f;
    #pragma unroll 8
    for (int d = 0; d < 128; d++)
        acc = fmaf(xm[d], W[(size_t)d * H_], acc);
    g_selhp[(b * 8 + c) * H_ + h] = acc;
}

// ---------------- fit partials: (B, S, 2 d-halves) ----------------
__global__ void k_fitp(const float* __restrict__ schema_emb, const float* __restrict__ Wf1) {
    int b = blockIdx.x, s = blockIdx.y, c = blockIdx.z;
    int h = threadIdx.x;
    __shared__ float fin[512];
    for (int i = h; i < 512; i += H_) {
        int d = c * 512 + i;
        fin[i] = schema_emb[s * D_ + d] + g_xm[b * D_ + d];
    }
    __syncthreads();
    const float* W = Wf1 + ((size_t)s * D_ + c * 512) * H_ + h;
    float acc = 0.f;
    #pragma unroll 8
    for (int d = 0; d < 512; d++)
        acc = fmaf(fin[d], W[(size_t)d * H_], acc);
    g_fitp[((b * S_ + s) * 2 + c) * H_ + h] = acc;
}

__global__ void k_fitr(const float* __restrict__ bf1, const float* __restrict__ Wf2,
                       const float* __restrict__ bf2) {
    int b = blockIdx.x, s = blockIdx.y;
    int h = threadIdx.x;
    float acc = g_fitp[((b * S_ + s) * 2 + 0) * H_ + h]
              + g_fitp[((b * S_ + s) * 2 + 1) * H_ + h] + bf1[s * H_ + h];
    float v = gelu_f(acc) * Wf2[s * H_ + h];
    #pragma unroll
    for (int o = 16; o > 0; o >>= 1) v += __shfl_xor_sync(0xffffffffu, v, o);
    __shared__ float rs[8];
    if ((threadIdx.x & 31) == 0) rs[threadIdx.x >> 5] = v;
    __syncthreads();
    if (threadIdx.x == 0) {
        float t = 0.f;
        #pragma unroll
        for (int w = 0; w < 8; w++) t += rs[w];
        g_fit[b * S_ + s] = sigmoid_f(t + bf2[s]);
    }
}

// ---------------- selection (combines selh partials, then softmax) ----------------
__global__ void k_sel2(const float* __restrict__ bsel1, const float* __restrict__ Wsel2,
                       const float* __restrict__ bsel2,
                       float* __restrict__ out_fit, float* __restrict__ out_selw,
                       float* __restrict__ out_best) {
    int b = blockIdx.x;
    int tid = threadIdx.x;   // 256
    __shared__ float selh[H_];
    {
        float a = bsel1[tid];
        #pragma unroll
        for (int c = 0; c < 8; c++) a += g_selhp[(b * 8 + c) * H_ + tid];
        selh[tid] = gelu_f(a);
    }
    __syncthreads();
    if (tid < 32) {
        int s = tid;
        float acc = bsel2[s];
        #pragma unroll 8
        for (int h = 0; h < H_; h++)
            acc = fmaf(selh[h], Wsel2[h * S_ + s], acc);
        float fit = g_fit[b * S_ + s];
        float logit = acc + fit;
        float m = logit;
        #pragma unroll
        for (int o = 16; o > 0; o >>= 1) m = fmaxf(m, __shfl_xor_sync(0xffffffffu, m, o));
        float e = expf(logit - m);
        float sum = e;
        #pragma unroll
        for (int o = 16; o > 0; o >>= 1) sum += __shfl_xor_sync(0xffffffffu, sum, o);
        float w = e / sum;
        g_selw[b * S_ + s] = w;
        out_selw[b * S_ + s] = w;
        out_fit[b * S_ + s] = fit;
        float mw = w;
        #pragma unroll
        for (int o = 16; o > 0; o >>= 1) mw = fmaxf(mw, __shfl_xor_sync(0xffffffffu, mw, o));
        unsigned mask = __ballot_sync(0xffffffffu, w == mw);
        if (s == 0) out_best[b] = (float)(__ffs(mask) - 1);
    }
}

// ---------------- role_bias partials: (SR, 8 d-chunks) ----------------
__global__ void k_rbp(const float* __restrict__ role_emb, const float* __restrict__ Wr1r) {
    int sr = blockIdx.x, c = blockIdx.y;
    int h = threadIdx.x;
    __shared__ float re[128];
    if (h < 128) re[h] = role_emb[sr * D_ + c * 128 + h];
    __syncthreads();
    const float* W = Wr1r + ((size_t)sr * D_ + c * 128) * H_ + h;
    float acc = 0.f;
    #pragma unroll 8
    for (int d = 0; d < 128; d++)
        acc = fmaf(re[d], W[(size_t)d * H_], acc);
    g_rbp[(sr * 8 + c) * H_ + h] = acc;
}

// ---------------- THE BIG KERNEL: mma.sync bf16 GEMM + fused epilogue ----------------
// CTA: M=128 tokens x N=128 H-half. 8 warps (2x4), warp tile 64x32, 3-stage cp.async.
// A smem: 128 rows x 128B (64 d), swizzle (row*8 + (c^(row&7)))*16
// B smem: 64 d-rows x 256B (128 h), 16 chunks/row, swizzle chunk c -> c^(r&7)
#define STG     32768              // 16KB A + 16KB B per stage
#define RBS_OFF (3*STG)
#define W2_OFF  (RBS_OFF + 512)
#define RED_OFF (RBS_OFF + 1024)
#define SMTOT   (RBS_OFF + 1024 + 2048)

__global__ __launch_bounds__(256, 2) void k_big(const float* __restrict__ Wr2,
                                                const float* __restrict__ br1) {
    extern __shared__ char smem[];
    uint32_t sb = smem_u32(smem);
    int tid = threadIdx.x;
    int lane = tid & 31, wid = tid >> 5;
    int wr = wid >> 2, wc = wid & 3;        // warp grid 2x4
    int mtile = blockIdx.x;                 // 0..31
    int nh = blockIdx.y;                    // 0..1
    int sr = blockIdx.z;                    // 0..191

    const __nv_bfloat16* Ag = g_xbf + (size_t)mtile * 128 * D_;
    const __nv_bfloat16* Bg = g_wbf + (size_t)sr * D_ * H_ + nh * 128;  // [d][h] rows

    float* rbs = (float*)(smem + RBS_OFF);
    float* w2s = (float*)(smem + W2_OFF);
    float* red = (float*)(smem + RED_OFF);
    if (tid < 128) {
        int hg = nh * 128 + tid;
        float rb = br1[sr * H_ + hg];
        #pragma unroll
        for (int c = 0; c < 8; c++) rb += g_rbp[(sr * 8 + c) * H_ + hg];
        rbs[tid] = rb;
        w2s[tid] = Wr2[sr * H_ + hg];
    }

    // prologue: stages 0..2
    #pragma unroll
    for (int st = 0; st < 3; st++) {
        uint32_t As = sb + st * STG, Bs = As + 16384;
        #pragma unroll
        for (int i = 0; i < 4; i++) {
            int idx = i * 256 + tid;
            { // A: 1024 chunks, r=token row (128), c=16B chunk (8 of them)
                int r = idx >> 3, c = idx & 7;
                uint32_t off = (uint32_t)(r * 8 + (c ^ (r & 7))) * 16;
                cpa16(As + off, Ag + (size_t)r * D_ + st * 64 + c * 8);
            }
            { // B: 1024 chunks, r=d row (64), c=16B chunk (16 of them)
                int r = idx >> 4, c = idx & 15;
                uint32_t off = (uint32_t)(r * 16 + (c ^ (r & 7))) * 16;
                cpa16(Bs + off, Bg + (size_t)(st * 64 + r) * H_ + c * 8);
            }
        }
        CP_COMMIT();
    }

    int g8 = lane >> 3, rr = lane & 7;
    int arow = rr + (g8 & 1) * 8;
    int coff = g8 >> 1;

    float acc[4][4][4];
    #pragma unroll
    for (int mt = 0; mt < 4; mt++)
        #pragma unroll
        for (int nt = 0; nt < 4; nt++)
            #pragma unroll
            for (int q = 0; q < 4; q++) acc[mt][nt][q] = 0.f;

    for (int kc = 0; kc < 16; kc++) {
        int rem = 15 - kc;
        if (rem >= 2)      { CP_WAIT(2); }
        else if (rem == 1) { CP_WAIT(1); }
        else               { CP_WAIT(0); }
        __syncthreads();
        int st = kc % 3;
        uint32_t Asb = sb + st * STG, Bsb = Asb + 16384;

        #pragma unroll
        for (int ks = 0; ks < 4; ks++) {
            // A frags (unchanged): rows = token, chunk c = ks*2+coff
            int c = ks * 2 + coff;
            uint32_t sw = (uint32_t)((c ^ rr) * 16);
            uint32_t a[4][4];
            #pragma unroll
            for (int mt = 0; mt < 4; mt++)
                ldm_x4(a[mt], Asb + (uint32_t)(wr * 64 + mt * 16 + arow) * 128 + sw);
            // B frags via ldmatrix.trans on [d][h] tile:
            // tile order: (k0-7,j),(k0-7,j+1),(k8-15,j),(k8-15,j+1)
            uint32_t bv[2][4];
            #pragma unroll
            for (int nt2 = 0; nt2 < 2; nt2++) {
                int jbase = wc * 4 + nt2 * 2;
                int drow = ks * 16 + (g8 >> 1) * 8 + rr;
                int chnk = (jbase + (g8 & 1)) ^ (drow & 7);
                ldm_x4_t(bv[nt2], Bsb + (uint32_t)(drow * 16 + chnk) * 16);
            }
            #pragma unroll
            for (int mt = 0; mt < 4; mt++)
                #pragma unroll
                for (int nt = 0; nt < 4; nt++)
                    mma16816(acc[mt][nt], a[mt], bv[nt >> 1][nt & 1], bv[nt >> 1][(nt & 1) + 2]);
        }
        __syncthreads();
        if (kc + 3 < 16) {
            int kn = kc + 3;
            uint32_t As = sb + st * STG, Bs = As + 16384;
            #pragma unroll
            for (int i = 0; i < 4; i++) {
                int idx = i * 256 + tid;
                {
                    int r = idx >> 3, c = idx & 7;
                    uint32_t off = (uint32_t)(r * 8 + (c ^ (r & 7))) * 16;
                    cpa16(As + off, Ag + (size_t)r * D_ + kn * 64 + c * 8);
                }
                {
                    int r = idx >> 4, c = idx & 15;
                    uint32_t off = (uint32_t)(r * 16 + (c ^ (r & 7))) * 16;
                    cpa16(Bs + off, Bg + (size_t)(kn * 64 + r) * H_ + c * 8);
                }
            }
            CP_COMMIT();
        }
    }

    // epilogue: gelu + Wr2-dot + reductions
    #pragma unroll
    for (int mt = 0; mt < 4; mt++) {
        float pA = 0.f, pB = 0.f;
        #pragma unroll
        for (int nt = 0; nt < 4; nt++) {
            int h0 = wc * 32 + nt * 8 + (lane & 3) * 2;
            float rb0 = rbs[h0], rb1 = rbs[h0 + 1];
            float w20 = w2s[h0], w21 = w2s[h0 + 1];
            pA = fmaf(gelu_f(acc[mt][nt][0] + rb0), w20, pA);
            pA = fmaf(gelu_f(acc[mt][nt][1] + rb1), w21, pA);
            pB = fmaf(gelu_f(acc[mt][nt][2] + rb0), w20, pB);
            pB = fmaf(gelu_f(acc[mt][nt][3] + rb1), w21, pB);
        }
        pA += __shfl_xor_sync(0xffffffffu, pA, 1);
        pA += __shfl_xor_sync(0xffffffffu, pA, 2);
        pB += __shfl_xor_sync(0xffffffffu, pB, 1);
        pB += __shfl_xor_sync(0xffffffffu, pB, 2);
        if ((lane & 3) == 0) {
            int row = wr * 64 + mt * 16 + (lane >> 2);
            red[wc * 128 + row] = pA;
            red[wc * 128 + row + 8] = pB;
        }
    }
    __syncthreads();
    if (tid < 128) {
        float p = red[tid] + red[128 + tid] + red[256 + tid] + red[384 + tid];
        int grow = mtile * 128 + tid;
        int b = grow >> 10, l = grow & 1023;
        int sch = sr / R_, rrole = sr % R_;
        g_part[(size_t)nh * SCORE_TOT + ((size_t)(b * S_ + sch) * R_ + rrole) * L_ + l] = p;
    }
}

// ---------------- refinement: combine partials + sigmoid, 3 iters, filler softmax ----
__device__ __forceinline__ void breduce6(float* v, float (*sm)[8], int is_sum) {
    int lane = threadIdx.x & 31, w = threadIdx.x >> 5;
    #pragma unroll
    for (int r = 0; r < 6; r++) {
        float t = v[r];
        #pragma unroll
        for (int o = 16; o > 0; o >>= 1) {
            float u = __shfl_xor_sync(0xffffffffu, t, o);
            t = is_sum ? (t + u) : fmaxf(t, u);
        }
        if (lane == 0) sm[r][w] = t;
    }
    __syncthreads();
    #pragma unroll
    for (int r = 0; r < 6; r++) {
        float t = sm[r][0];
        #pragma unroll
        for (int w2 = 1; w2 < 8; w2++) t = is_sum ? (t + sm[r][w2]) : fmaxf(t, sm[r][w2]);
        v[r] = t;
    }
    __syncthreads();
}

__global__ __launch_bounds__(256) void k_refine(const float* __restrict__ br2) {
    int b = blockIdx.x, s = blockIdx.y;
    size_t base = (size_t)(b * S_ + s) * R_ * L_;
    int l0 = threadIdx.x;
    __shared__ float red[6][8];
    float sc[6][4];
    #pragma unroll
    for (int r = 0; r < 6; r++) {
        float bias = br2[s * R_ + r];
        #pragma unroll
        for (int j = 0; j < 4; j++) {
            size_t idx = base + r * L_ + l0 + j * 256;
            sc[r][j] = sigmoid_f(g_part[idx] + g_part[SCORE_TOT + idx] + bias);
        }
    }

    const float inv = 0.03125f;
    for (int it = 0; it < 3; it++) {
        float rp[6][4];
        #pragma unroll
        for (int j = 0; j < 4; j++) {
            float m = sc[0][j];
            #pragma unroll
            for (int r = 1; r < 6; r++) m = fmaxf(m, sc[r][j]);
            float sum = 0.f;
            #pragma unroll
            for (int r = 0; r < 6; r++) { rp[r][j] = expf(sc[r][j] - m); sum += rp[r][j]; }
            float isum = 1.f / sum;
            #pragma unroll
            for (int r = 0; r < 6; r++) rp[r][j] *= isum;
        }
        float mx[6];
        #pragma unroll
        for (int r = 0; r < 6; r++) {
            mx[r] = sc[r][0];
            #pragma unroll
            for (int j = 1; j < 4; j++) mx[r] = fmaxf(mx[r], sc[r][j]);
        }
        breduce6(mx, red, 0);
        float tp[6][4], sums[6];
        #pragma unroll
        for (int r = 0; r < 6; r++) {
            sums[r] = 0.f;
            #pragma unroll
            for (int j = 0; j < 4; j++) { tp[r][j] = expf((sc[r][j] - mx[r]) * inv); sums[r] += tp[r][j]; }
        }
        breduce6(sums, red, 1);
        #pragma unroll
        for (int r = 0; r < 6; r++) {
            float isum = 1.f / sums[r];
            #pragma unroll
            for (int j = 0; j < 4; j++)
                sc[r][j] = rp[r][j] * (tp[r][j] * isum) * sc[r][j];
        }
    }
    float mx[6];
    #pragma unroll
    for (int r = 0; r < 6; r++) {
        mx[r] = sc[r][0];
        #pragma unroll
        for (int j = 1; j < 4; j++) mx[r] = fmaxf(mx[r], sc[r][j]);
    }
    breduce6(mx, red, 0);
    float e[6][4], sums[6];
    #pragma unroll
    for (int r = 0; r < 6; r++) {
        sums[r] = 0.f;
        #pragma unroll
        for (int j = 0; j < 4; j++) { e[r][j] = expf(sc[r][j] - mx[r]); sums[r] += e[r][j]; }
    }
    breduce6(sums, red, 1);
    #pragma unroll
    for (int r = 0; r < 6; r++) {
        float isum = 1.f / sums[r];
        #pragma unroll
        for (int j = 0; j < 4; j++)
            g_scores[base + r * L_ + l0 + j * 256] = e[r][j] * isum;
    }
}

// ---------------- cw[b,r,l] = sum_s selw * fw ----------------
__global__ void k_cw() {
    int idx = blockIdx.x * 256 + threadIdx.x;
    int b = idx / (R_ * L_);
    int rl = idx % (R_ * L_);
    int r = rl / L_, l = rl % L_;
    float acc = 0.f;
    #pragma unroll 8
    for (int s = 0; s < S_; s++)
        acc = fmaf(g_selw[b * S_ + s], g_scores[((size_t)(b * S_ + s) * R_ + r) * L_ + l], acc);
    g_cw[idx] = acc;
}

// ---------------- bound_weighted ----------------
__global__ __launch_bounds__(256) void k_bw(const float* __restrict__ x, float* __restrict__ out_bw) {
    int b = blockIdx.x, dblk = blockIdx.y;
    int dl = threadIdx.x & 63, ph = threadIdx.x >> 6;
    int d = dblk * 64 + dl;
    __shared__ float cw[R_ * L_];
    for (int i = threadIdx.x; i < R_ * L_; i += 256) cw[i] = g_cw[b * R_ * L_ + i];
    __syncthreads();
    float acc[6] = {0.f, 0.f, 0.f, 0.f, 0.f, 0.f};
    for (int l = ph * 256; l < ph * 256 + 256; l++) {
        float xv = x[((size_t)b * L_ + l) * D_ + d];
        #pragma unroll
        for (int r = 0; r < 6; r++) acc[r] = fmaf(cw[r * L_ + l], xv, acc[r]);
    }
    __shared__ float red[6][4][64];
    #pragma unroll
    for (int r = 0; r < 6; r++) red[r][ph][dl] = acc[r];
    __syncthreads();
    if (ph == 0) {
        #pragma unroll
        for (int r = 0; r < 6; r++) {
            float t = red[r][0][dl] + red[r][1][dl] + red[r][2][dl] + red[r][3][dl];
            g_bw[(b * R_ + r) * D_ + d] = t;
            out_bw[(b * R_ + r) * D_ + d] = t;
        }
    }
}

// ---------------- projection MLP ----------------
__global__ void k_p1(const float* __restrict__ Wp1, const float* __restrict__ bp1) {
    int b = blockIdx.x;
    int j = blockIdx.y * 256 + threadIdx.x;
    __shared__ float bf[R_ * D_];
    for (int i = threadIdx.x; i < R_ * D_; i += 256) bf[i] = g_bw[b * R_ * D_ + i];
    __syncthreads();
    float acc = bp1[j];
    #pragma unroll 8
    for (int i = 0; i < R_ * D_; i++)
        acc = fmaf(bf[i], Wp1[(size_t)i * (2 * H_) + j], acc);
    g_hid[b * (2 * H_) + j] = gelu_f(acc);
}

__global__ void k_p2(const float* __restrict__ Wp2, const float* __restrict__ bp2) {
    int b = blockIdx.x;
    __shared__ float hd[2 * H_];
    for (int i = threadIdx.x; i < 2 * H_; i += 256) hd[i] = g_hid[b * (2 * H_) + i];
    __syncthreads();
    #pragma unroll
    for (int dd = 0; dd < 4; dd++) {
        int d = dd * 256 + threadIdx.x;
        float acc = bp2[d];
        #pragma unroll 8
        for (int j = 0; j < 2 * H_; j++)
            acc = fmaf(hd[j], Wp2[(size_t)j * D_ + d], acc);
        g_repr[b * D_ + d] = acc;
    }
}

// ---------------- final residual + RMSNorm ----------------
__global__ __launch_bounds__(256) void k_final(const float* __restrict__ x,
                                               const float* __restrict__ norm_w,
                                               float* __restrict__ out_xs) {
    int row = blockIdx.x;
    int b = row >> 10;
    const float4* xr = (const float4*)(x + (size_t)row * D_);
    const float4* rp = (const float4*)(g_repr + (size_t)b * D_);
    const float4* nw = (const float4*)norm_w;
    float4 v = xr[threadIdx.x];
    float4 r = rp[threadIdx.x];
    v.x = fmaf(0.1f, r.x, v.x); v.y = fmaf(0.1f, r.y, v.y);
    v.z = fmaf(0.1f, r.z, v.z); v.w = fmaf(0.1f, r.w, v.w);
    float ss = v.x * v.x + v.y * v.y + v.z * v.z + v.w * v.w;
    #pragma unroll
    for (int o = 16; o > 0; o >>= 1) ss += __shfl_xor_sync(0xffffffffu, ss, o);
    __shared__ float rs[8];
    if ((threadIdx.x & 31) == 0) rs[threadIdx.x >> 5] = ss;
    __syncthreads();
    float tot = rs[0] + rs[1] + rs[2] + rs[3] + rs[4] + rs[5] + rs[6] + rs[7];
    float scale = rsqrtf(tot * (1.0f / (float)D_) + 1e-6f);
    float4 w = nw[threadIdx.x];
    float4 o;
    o.x = v.x * scale * w.x; o.y = v.y * scale * w.y;
    o.z = v.z * scale * w.z; o.w = v.w * scale * w.w;
    ((float4*)out_xs)[(size_t)row * 256 + threadIdx.x] = o;
}

// ---------------- launch ----------------
extern "C" void kernel_launch(void* const* d_in, const int* in_sizes, int n_in,
                              void* d_out, int out_size) {
    const float* x          = (const float*)d_in[0];
    const float* role_emb   = (const float*)d_in[1];
    const float* Wr1x       = (const float*)d_in[2];
    const float* Wr1r       = (const float*)d_in[3];
    const float* br1        = (const float*)d_in[4];
    const float* Wr2        = (const float*)d_in[5];
    const float* br2        = (const float*)d_in[6];
    const float* schema_emb = (const float*)d_in[7];
    const float* Wf1        = (const float*)d_in[8];
    const float* bf1        = (const float*)d_in[9];
    const float* Wf2        = (const float*)d_in[10];
    const float* bf2        = (const float*)d_in[11];
    const float* Wp1        = (const float*)d_in[12];
    const float* bp1        = (const float*)d_in[13];
    const float* Wp2        = (const float*)d_in[14];
    const float* bp2        = (const float*)d_in[15];
    const float* Wsel1      = (const float*)d_in[16];
    const float* bsel1      = (const float*)d_in[17];
    const float* Wsel2      = (const float*)d_in[18];
    const float* bsel2      = (const float*)d_in[19];
    const float* norm_w     = (const float*)d_in[20];

    float* out      = (float*)d_out;
    float* out_xs   = out;
    float* out_fit  = out + (size_t)B_ * L_ * D_;
    float* out_selw = out_fit + B_ * S_;
    float* out_best = out_selw + B_ * S_;
    float* out_bw   = out_best + B_;

    cudaFuncSetAttribute(k_big, cudaFuncAttributeMaxDynamicSharedMemorySize, SMTOT);

    k_cvt_x<<<M_ * D_ / 1024, 256>>>(x);
    k_cvt_w<<<(int)(((size_t)SR_ * D_ * H_) / 2048), 256>>>(Wr1x);
    k_xm<<<dim3(B_, 32), 128>>>(x);
    k_selhp<<<dim3(B_, 8), 256>>>(Wsel1);
    k_fitp<<<dim3(B_, S_, 2), 256>>>(schema_emb, Wf1);
    k_fitr<<<dim3(B_, S_), 256>>>(bf1, Wf2, bf2);
    k_sel2<<<B_, 256>>>(bsel1, Wsel2, bsel2, out_fit, out_selw, out_best);
    k_rbp<<<dim3(SR_, 8), 256>>>(role_emb, Wr1r);
    k_big<<<dim3(32, 2, SR_), 256, SMTOT>>>(Wr2, br1);
    k_refine<<<dim3(B_, S_), 256>>>(br2);
    k_cw<<<(B_ * R_ * L_) / 256, 256>>>();
    k_bw<<<dim3(B_, 16), 256>>>(x, out_bw);
    k_p1<<<dim3(B_, 2), 256>>>(Wp1, bp1);
    k_p2<<<B_, 256>>>(Wp2, bp2);
    k_final<<<M_, 256>>>(x, norm_w, out_xs);
}

// round 6
// speedup vs baseline: 5.8887x; 1.2893x over previous
#include <cuda_runtime.h>
#include <cuda_bf16.h>
#include <cstdint>
#include <math.h>

#define B_ 4
#define L_ 1024
#define D_ 1024
#define S_ 32
#define R_ 6
#define H_ 256
#define SR_ (S_*R_)       // 192
#define M_ (B_*L_)        // 4096
#define SCORE_TOT (B_*S_*R_*L_)

// ---------------- scratch (device globals; no allocation allowed) ----------------
static __device__ float g_rbp[SR_*8*H_];
static __device__ float g_scores[SCORE_TOT];
static __device__ float g_part[2*SCORE_TOT];
static __device__ float g_xm[B_*D_];
static __device__ float g_fit[B_*S_];
static __device__ float g_fitp[B_*S_*2*H_];
static __device__ float g_selhp[B_*8*H_];
static __device__ float g_selw[B_*S_];
static __device__ float g_cw[B_*R_*L_];
static __device__ float g_bw[B_*R_*D_];
static __device__ float g_hidp[B_*6*512];
static __device__ float g_repr[B_*D_];
static __device__ __align__(256) unsigned char g_xf8[M_*D_];              // 4 MB  [token][d]
static __device__ __align__(256) unsigned char g_wf8[(size_t)SR_*H_*D_];  // 50 MB [sr][h][d]

__device__ __forceinline__ float gelu_f(float v) {
    return 0.5f * v * (1.0f + erff(v * 0.70710678118654752440f));
}
__device__ __forceinline__ float sigmoid_f(float v) {
    return 1.0f / (1.0f + expf(-v));
}

// ---------------- primitives (sm_89-era, legal on compute_103 base) --------------
__device__ __forceinline__ uint32_t smem_u32(const void* p) {
    uint32_t a;
    asm("{ .reg .u64 t; cvta.to.shared.u64 t, %1; cvt.u32.u64 %0, t; }" : "=r"(a) : "l"(p));
    return a;
}
__device__ __forceinline__ void cpa16(uint32_t dst, const void* src) {
    asm volatile("cp.async.cg.shared.global [%0], [%1], 16;" :: "r"(dst), "l"(src));
}
#define CP_COMMIT() asm volatile("cp.async.commit_group;" ::: "memory")
#define CP_WAIT(n)  asm volatile("cp.async.wait_group %0;" :: "n"(n) : "memory")

__device__ __forceinline__ void ldm_x4(uint32_t* r, uint32_t addr) {
    asm volatile("ldmatrix.sync.aligned.m8n8.x4.shared.b16 {%0,%1,%2,%3}, [%4];"
        : "=r"(r[0]), "=r"(r[1]), "=r"(r[2]), "=r"(r[3]) : "r"(addr));
}
// fp8 e4m3 mma: D(16x8 f32) += A(16x32 e4m3, row) x B(32x8 e4m3, col)
__device__ __forceinline__ void mma_fp8(float* d, const uint32_t* a, uint32_t b0, uint32_t b1) {
    asm volatile("mma.sync.aligned.m16n8k32.row.col.f32.e4m3.e4m3.f32 "
        "{%0,%1,%2,%3}, {%4,%5,%6,%7}, {%8,%9}, {%0,%1,%2,%3};"
        : "+f"(d[0]), "+f"(d[1]), "+f"(d[2]), "+f"(d[3])
        : "r"(a[0]), "r"(a[1]), "r"(a[2]), "r"(a[3]), "r"(b0), "r"(b1));
}
// pack 2 floats -> e4m3x2 (lo = second arg)
__device__ __forceinline__ uint16_t f2e4m3x2(float hi, float lo) {
    uint16_t v;
    asm("cvt.rn.satfinite.e4m3x2.f32 %0, %1, %2;" : "=h"(v) : "f"(hi), "f"(lo));
    return v;
}

// ---------------- fp8 conversions ----------------
__global__ void k_cvt_x(const float* __restrict__ x) {
    size_t i = ((size_t)blockIdx.x * 256 + threadIdx.x) * 8;
    float4 v0 = *(const float4*)(x + i);
    float4 v1 = *(const float4*)(x + i + 4);
    uint32_t lo = (uint32_t)f2e4m3x2(v0.y, v0.x) | ((uint32_t)f2e4m3x2(v0.w, v0.z) << 16);
    uint32_t hi = (uint32_t)f2e4m3x2(v1.y, v1.x) | ((uint32_t)f2e4m3x2(v1.w, v1.z) << 16);
    *(uint2*)(g_xf8 + i) = make_uint2(lo, hi);
}

// Wr1x [sr][d][h] fp32 -> g_wf8 [sr][h][d] e4m3 (32h x 128d tile transpose)
__global__ __launch_bounds__(256) void k_cvt_w(const float* __restrict__ W) {
    __shared__ float t[32][129];
    int sr = blockIdx.x, db = blockIdx.y, hb = blockIdx.z;   // (192, 8, 8)
    int tx = threadIdx.x & 31, ty = threadIdx.x >> 5;
    const float* Wp = W + ((size_t)sr * D_ + db * 128) * H_ + hb * 32;
    #pragma unroll
    for (int i = 0; i < 16; i++) {
        int dr = i * 8 + ty;
        t[tx][dr] = Wp[(size_t)dr * H_ + tx];
    }
    __syncthreads();
    unsigned char* Op = g_wf8 + ((size_t)sr * H_ + hb * 32) * D_ + db * 128;
    #pragma unroll
    for (int j = 0; j < 4; j++) {
        int h = ty * 4 + j;
        uint32_t v = (uint32_t)f2e4m3x2(t[h][tx * 4 + 1], t[h][tx * 4])
                   | ((uint32_t)f2e4m3x2(t[h][tx * 4 + 3], t[h][tx * 4 + 2]) << 16);
        *(uint32_t*)(Op + (size_t)h * D_ + tx * 4) = v;
    }
}

// ---------------- xm = mean over L ----------------
__global__ void k_xm(const float* __restrict__ x) {
    int b = blockIdx.x, dc = blockIdx.y;
    int dl = threadIdx.x & 31, ph = threadIdx.x >> 5;
    int d = dc * 32 + dl;
    float s = 0.f;
    for (int l = ph; l < L_; l += 4)
        s += x[((size_t)b * L_ + l) * D_ + d];
    __shared__ float sm[4][32];
    sm[ph][dl] = s;
    __syncthreads();
    if (ph == 0) {
        float t = sm[0][dl] + sm[1][dl] + sm[2][dl] + sm[3][dl];
        g_xm[b * D_ + d] = t * (1.0f / (float)L_);
    }
}

// ---------------- sel hidden partials: (B, 8 d-chunks) ----------------
__global__ void k_selhp(const float* __restrict__ Wsel1) {
    int b = blockIdx.x, c = blockIdx.y;
    int h = threadIdx.x;
    __shared__ float xm[128];
    if (h < 128) xm[h] = g_xm[b * D_ + c * 128 + h];
    __syncthreads();
    const float* W = Wsel1 + (size_t)(c * 128) * H_ + h;
    float acc = 0.f;
    #pragma unroll 8
    for (int d = 0; d < 128; d++)
        acc = fmaf(xm[d], W[(size_t)d * H_], acc);
    g_selhp[(b * 8 + c) * H_ + h] = acc;
}

// ---------------- fit partials: (B, S, 2 d-halves) ----------------
__global__ void k_fitp(const float* __restrict__ schema_emb, const float* __restrict__ Wf1) {
    int b = blockIdx.x, s = blockIdx.y, c = blockIdx.z;
    int h = threadIdx.x;
    __shared__ float fin[512];
    for (int i = h; i < 512; i += H_) {
        int d = c * 512 + i;
        fin[i] = schema_emb[s * D_ + d] + g_xm[b * D_ + d];
    }
    __syncthreads();
    const float* W = Wf1 + ((size_t)s * D_ + c * 512) * H_ + h;
    float acc = 0.f;
    #pragma unroll 8
    for (int d = 0; d < 512; d++)
        acc = fmaf(fin[d], W[(size_t)d * H_], acc);
    g_fitp[((b * S_ + s) * 2 + c) * H_ + h] = acc;
}

__global__ void k_fitr(const float* __restrict__ bf1, const float* __restrict__ Wf2,
                       const float* __restrict__ bf2) {
    int b = blockIdx.x, s = blockIdx.y;
    int h = threadIdx.x;
    float acc = g_fitp[((b * S_ + s) * 2 + 0) * H_ + h]
              + g_fitp[((b * S_ + s) * 2 + 1) * H_ + h] + bf1[s * H_ + h];
    float v = gelu_f(acc) * Wf2[s * H_ + h];
    #pragma unroll
    for (int o = 16; o > 0; o >>= 1) v += __shfl_xor_sync(0xffffffffu, v, o);
    __shared__ float rs[8];
    if ((threadIdx.x & 31) == 0) rs[threadIdx.x >> 5] = v;
    __syncthreads();
    if (threadIdx.x == 0) {
        float t = 0.f;
        #pragma unroll
        for (int w = 0; w < 8; w++) t += rs[w];
        g_fit[b * S_ + s] = sigmoid_f(t + bf2[s]);
    }
}

// ---------------- selection ----------------
__global__ void k_sel2(const float* __restrict__ bsel1, const float* __restrict__ Wsel2,
                       const float* __restrict__ bsel2,
                       float* __restrict__ out_fit, float* __restrict__ out_selw,
                       float* __restrict__ out_best) {
    int b = blockIdx.x;
    int tid = threadIdx.x;   // 256
    __shared__ float selh[H_];
    {
        float a = bsel1[tid];
        #pragma unroll
        for (int c = 0; c < 8; c++) a += g_selhp[(b * 8 + c) * H_ + tid];
        selh[tid] = gelu_f(a);
    }
    __syncthreads();
    if (tid < 32) {
        int s = tid;
        float acc = bsel2[s];
        #pragma unroll 8
        for (int h = 0; h < H_; h++)
            acc = fmaf(selh[h], Wsel2[h * S_ + s], acc);
        float fit = g_fit[b * S_ + s];
        float logit = acc + fit;
        float m = logit;
        #pragma unroll
        for (int o = 16; o > 0; o >>= 1) m = fmaxf(m, __shfl_xor_sync(0xffffffffu, m, o));
        float e = expf(logit - m);
        float sum = e;
        #pragma unroll
        for (int o = 16; o > 0; o >>= 1) sum += __shfl_xor_sync(0xffffffffu, sum, o);
        float w = e / sum;
        g_selw[b * S_ + s] = w;
        out_selw[b * S_ + s] = w;
        out_fit[b * S_ + s] = fit;
        float mw = w;
        #pragma unroll
        for (int o = 16; o > 0; o >>= 1) mw = fmaxf(mw, __shfl_xor_sync(0xffffffffu, mw, o));
        unsigned mask = __ballot_sync(0xffffffffu, w == mw);
        if (s == 0) out_best[b] = (float)(__ffs(mask) - 1);
    }
}

// ---------------- role_bias partials: (SR, 8 d-chunks) ----------------
__global__ void k_rbp(const float* __restrict__ role_emb, const float* __restrict__ Wr1r) {
    int sr = blockIdx.x, c = blockIdx.y;
    int h = threadIdx.x;
    __shared__ float re[128];
    if (h < 128) re[h] = role_emb[sr * D_ + c * 128 + h];
    __syncthreads();
    const float* W = Wr1r + ((size_t)sr * D_ + c * 128) * H_ + h;
    float acc = 0.f;
    #pragma unroll 8
    for (int d = 0; d < 128; d++)
        acc = fmaf(re[d], W[(size_t)d * H_], acc);
    g_rbp[(sr * 8 + c) * H_ + h] = acc;
}

// ---------------- THE BIG KERNEL: fp8 mma.sync GEMM + fused epilogue ----------------
// CTA: M=128 tokens x N=128 H-half, K=1024 in 8 chunks of 128, 3-stage cp.async.
// A smem: 128 token-rows x 128B (128 d fp8); B smem: 128 h-rows x 128B (128 d fp8)
// swizzle: byte_off(row, c16) = (row*8 + (c16 ^ (row&7))) * 16
#define STG     32768              // 16KB A + 16KB B per stage
#define RBS_OFF (3*STG)
#define W2_OFF  (RBS_OFF + 512)
#define RED_OFF (RBS_OFF + 1024)
#define SMTOT   (RBS_OFF + 1024 + 2048)

__global__ __launch_bounds__(256, 2) void k_big(const float* __restrict__ Wr2,
                                                const float* __restrict__ br1) {
    extern __shared__ char smem[];
    uint32_t sb = smem_u32(smem);
    int tid = threadIdx.x;
    int lane = tid & 31, wid = tid >> 5;
    int wr = wid >> 2, wc = wid & 3;        // warp grid 2x4
    int mtile = blockIdx.x;                 // 0..31
    int nh = blockIdx.y;                    // 0..1
    int sr = blockIdx.z;                    // 0..191

    const unsigned char* Ag = g_xf8 + (size_t)mtile * 128 * D_;
    const unsigned char* Bg = g_wf8 + ((size_t)sr * H_ + nh * 128) * D_;

    float* rbs = (float*)(smem + RBS_OFF);
    float* w2s = (float*)(smem + W2_OFF);
    float* red = (float*)(smem + RED_OFF);
    if (tid < 128) {
        int hg = nh * 128 + tid;
        float rb = br1[sr * H_ + hg];
        #pragma unroll
        for (int c = 0; c < 8; c++) rb += g_rbp[(sr * 8 + c) * H_ + hg];
        rbs[tid] = rb;
        w2s[tid] = Wr2[sr * H_ + hg];
    }

    // prologue: stages 0..2 (K chunks 0..2, 128 d each)
    #pragma unroll
    for (int st = 0; st < 3; st++) {
        uint32_t As = sb + st * STG, Bs = As + 16384;
        #pragma unroll
        for (int i = 0; i < 4; i++) {
            int idx = i * 256 + tid;            // 0..1023
            int r = idx >> 3, c = idx & 7;
            uint32_t off = (uint32_t)(r * 8 + (c ^ (r & 7))) * 16;
            cpa16(As + off, Ag + (size_t)r * D_ + st * 128 + c * 16);
            cpa16(Bs + off, Bg + (size_t)r * D_ + st * 128 + c * 16);
        }
        CP_COMMIT();
    }

    int g8 = lane >> 3, rr = lane & 7;
    int arow = rr + (g8 & 1) * 8;          // row within 16-row tile
    int coff = g8 >> 1;                    // 16B chunk within 32B k-step

    float acc[4][4][4];
    #pragma unroll
    for (int mt = 0; mt < 4; mt++)
        #pragma unroll
        for (int nt = 0; nt < 4; nt++)
            #pragma unroll
            for (int q = 0; q < 4; q++) acc[mt][nt][q] = 0.f;

    for (int kc = 0; kc < 8; kc++) {
        int rem = 7 - kc;
        if (rem >= 2)      { CP_WAIT(2); }
        else if (rem == 1) { CP_WAIT(1); }
        else               { CP_WAIT(0); }
        __syncthreads();
        int st = kc % 3;
        uint32_t Asb = sb + st * STG, Bsb = Asb + 16384;

        #pragma unroll
        for (int ks = 0; ks < 4; ks++) {       // 4 k32-steps per 128-d chunk
            int c = ks * 2 + coff;
            uint32_t sw = (uint32_t)((c ^ rr) * 16);
            uint32_t a[4][4];
            #pragma unroll
            for (int mt = 0; mt < 4; mt++)
                ldm_x4(a[mt], Asb + (uint32_t)(wr * 64 + mt * 16 + arow) * 128 + sw);
            uint32_t bv[2][4];
            #pragma unroll
            for (int nt2 = 0; nt2 < 2; nt2++)
                ldm_x4(bv[nt2], Bsb + (uint32_t)(wc * 32 + nt2 * 16 + arow) * 128 + sw);
            #pragma unroll
            for (int mt = 0; mt < 4; mt++)
                #pragma unroll
                for (int nt = 0; nt < 4; nt++)
                    mma_fp8(acc[mt][nt], a[mt], bv[nt >> 1][nt & 1], bv[nt >> 1][(nt & 1) + 2]);
        }
        __syncthreads();
        if (kc + 3 < 8) {
            int kn = kc + 3;
            uint32_t As = sb + st * STG, Bs = As + 16384;
            #pragma unroll
            for (int i = 0; i < 4; i++) {
                int idx = i * 256 + tid;
                int r = idx >> 3, c = idx & 7;
                uint32_t off = (uint32_t)(r * 8 + (c ^ (r & 7))) * 16;
                cpa16(As + off, Ag + (size_t)r * D_ + kn * 128 + c * 16);
                cpa16(Bs + off, Bg + (size_t)r * D_ + kn * 128 + c * 16);
            }
            CP_COMMIT();
        }
    }

    // epilogue: gelu + Wr2-dot + reductions
    // C frag: c0=(row, h0), c1=(row, h0+1), c2=(row+8, h0), c3=(row+8, h0+1)
    // h0 = wc*32 + (nt>>1)*16 + (nt&1)*8 + (lane&3)*2
    #pragma unroll
    for (int mt = 0; mt < 4; mt++) {
        float pA = 0.f, pB = 0.f;
        #pragma unroll
        for (int nt = 0; nt < 4; nt++) {
            int h0 = wc * 32 + (nt >> 1) * 16 + (nt & 1) * 8 + (lane & 3) * 2;
            float rb0 = rbs[h0], rb1 = rbs[h0 + 1];
            float w20 = w2s[h0], w21 = w2s[h0 + 1];
            pA = fmaf(gelu_f(acc[mt][nt][0] + rb0), w20, pA);
            pA = fmaf(gelu_f(acc[mt][nt][1] + rb1), w21, pA);
            pB = fmaf(gelu_f(acc[mt][nt][2] + rb0), w20, pB);
            pB = fmaf(gelu_f(acc[mt][nt][3] + rb1), w21, pB);
        }
        pA += __shfl_xor_sync(0xffffffffu, pA, 1);
        pA += __shfl_xor_sync(0xffffffffu, pA, 2);
        pB += __shfl_xor_sync(0xffffffffu, pB, 1);
        pB += __shfl_xor_sync(0xffffffffu, pB, 2);
        if ((lane & 3) == 0) {
            int row = wr * 64 + mt * 16 + (lane >> 2);
            red[wc * 128 + row] = pA;
            red[wc * 128 + row + 8] = pB;
        }
    }
    __syncthreads();
    if (tid < 128) {
        float p = red[tid] + red[128 + tid] + red[256 + tid] + red[384 + tid];
        int grow = mtile * 128 + tid;
        int b = grow >> 10, l = grow & 1023;
        int sch = sr / R_, rrole = sr % R_;
        g_part[(size_t)nh * SCORE_TOT + ((size_t)(b * S_ + sch) * R_ + rrole) * L_ + l] = p;
    }
}

// ---------------- refinement: combine partials + sigmoid, 3 iters, filler softmax ----
__device__ __forceinline__ void breduce6(float* v, float (*sm)[8], int is_sum) {
    int lane = threadIdx.x & 31, w = threadIdx.x >> 5;
    #pragma unroll
    for (int r = 0; r < 6; r++) {
        float t = v[r];
        #pragma unroll
        for (int o = 16; o > 0; o >>= 1) {
            float u = __shfl_xor_sync(0xffffffffu, t, o);
            t = is_sum ? (t + u) : fmaxf(t, u);
        }
        if (lane == 0) sm[r][w] = t;
    }
    __syncthreads();
    #pragma unroll
    for (int r = 0; r < 6; r++) {
        float t = sm[r][0];
        #pragma unroll
        for (int w2 = 1; w2 < 8; w2++) t = is_sum ? (t + sm[r][w2]) : fmaxf(t, sm[r][w2]);
        v[r] = t;
    }
    __syncthreads();
}

__global__ __launch_bounds__(256) void k_refine(const float* __restrict__ br2) {
    int b = blockIdx.x, s = blockIdx.y;
    size_t base = (size_t)(b * S_ + s) * R_ * L_;
    int l0 = threadIdx.x;
    __shared__ float red[6][8];
    float sc[6][4];
    #pragma unroll
    for (int r = 0; r < 6; r++) {
        float bias = br2[s * R_ + r];
        #pragma unroll
        for (int j = 0; j < 4; j++) {
            size_t idx = base + r * L_ + l0 + j * 256;
            sc[r][j] = sigmoid_f(g_part[idx] + g_part[SCORE_TOT + idx] + bias);
        }
    }

    const float inv = 0.03125f;
    for (int it = 0; it < 3; it++) {
        float rp[6][4];
        #pragma unroll
        for (int j = 0; j < 4; j++) {
            float m = sc[0][j];
            #pragma unroll
            for (int r = 1; r < 6; r++) m = fmaxf(m, sc[r][j]);
            float sum = 0.f;
            #pragma unroll
            for (int r = 0; r < 6; r++) { rp[r][j] = expf(sc[r][j] - m); sum += rp[r][j]; }
            float isum = 1.f / sum;
            #pragma unroll
            for (int r = 0; r < 6; r++) rp[r][j] *= isum;
        }
        float mx[6];
        #pragma unroll
        for (int r = 0; r < 6; r++) {
            mx[r] = sc[r][0];
            #pragma unroll
            for (int j = 1; j < 4; j++) mx[r] = fmaxf(mx[r], sc[r][j]);
        }
        breduce6(mx, red, 0);
        float tp[6][4], sums[6];
        #pragma unroll
        for (int r = 0; r < 6; r++) {
            sums[r] = 0.f;
            #pragma unroll
            for (int j = 0; j < 4; j++) { tp[r][j] = expf((sc[r][j] - mx[r]) * inv); sums[r] += tp[r][j]; }
        }
        breduce6(sums, red, 1);
        #pragma unroll
        for (int r = 0; r < 6; r++) {
            float isum = 1.f / sums[r];
            #pragma unroll
            for (int j = 0; j < 4; j++)
                sc[r][j] = rp[r][j] * (tp[r][j] * isum) * sc[r][j];
        }
    }
    float mx[6];
    #pragma unroll
    for (int r = 0; r < 6; r++) {
        mx[r] = sc[r][0];
        #pragma unroll
        for (int j = 1; j < 4; j++) mx[r] = fmaxf(mx[r], sc[r][j]);
    }
    breduce6(mx, red, 0);
    float e[6][4], sums[6];
    #pragma unroll
    for (int r = 0; r < 6; r++) {
        sums[r] = 0.f;
        #pragma unroll
        for (int j = 0; j < 4; j++) { e[r][j] = expf(sc[r][j] - mx[r]); sums[r] += e[r][j]; }
    }
    breduce6(sums, red, 1);
    #pragma unroll
    for (int r = 0; r < 6; r++) {
        float isum = 1.f / sums[r];
        #pragma unroll
        for (int j = 0; j < 4; j++)
            g_scores[base + r * L_ + l0 + j * 256] = e[r][j] * isum;
    }
}

// ---------------- cw[b,r,l] = sum_s selw * fw ----------------
__global__ void k_cw() {
    int idx = blockIdx.x * 256 + threadIdx.x;
    int b = idx / (R_ * L_);
    int rl = idx % (R_ * L_);
    int r = rl / L_, l = rl % L_;
    float acc = 0.f;
    #pragma unroll 8
    for (int s = 0; s < S_; s++)
        acc = fmaf(g_selw[b * S_ + s], g_scores[((size_t)(b * S_ + s) * R_ + r) * L_ + l], acc);
    g_cw[idx] = acc;
}

// ---------------- bound_weighted ----------------
__global__ __launch_bounds__(256) void k_bw(const float* __restrict__ x, float* __restrict__ out_bw) {
    int b = blockIdx.x, dblk = blockIdx.y;
    int dl = threadIdx.x & 63, ph = threadIdx.x >> 6;
    int d = dblk * 64 + dl;
    __shared__ float cw[R_ * L_];
    for (int i = threadIdx.x; i < R_ * L_; i += 256) cw[i] = g_cw[b * R_ * L_ + i];
    __syncthreads();
    float acc[6] = {0.f, 0.f, 0.f, 0.f, 0.f, 0.f};
    for (int l = ph * 256; l < ph * 256 + 256; l++) {
        float xv = x[((size_t)b * L_ + l) * D_ + d];
        #pragma unroll
        for (int r = 0; r < 6; r++) acc[r] = fmaf(cw[r * L_ + l], xv, acc[r]);
    }
    __shared__ float red[6][4][64];
    #pragma unroll
    for (int r = 0; r < 6; r++) red[r][ph][dl] = acc[r];
    __syncthreads();
    if (ph == 0) {
        #pragma unroll
        for (int r = 0; r < 6; r++) {
            float t = red[r][0][dl] + red[r][1][dl] + red[r][2][dl] + red[r][3][dl];
            g_bw[(b * R_ + r) * D_ + d] = t;
            out_bw[(b * R_ + r) * D_ + d] = t;
        }
    }
}

// ---------------- projection MLP: partials (B, 2 j-halves, 6 i-chunks) ----------------
__global__ void k_p1(const float* __restrict__ Wp1) {
    int b = blockIdx.x, jb = blockIdx.y, c = blockIdx.z;
    int tid = threadIdx.x;
    __shared__ float bf[1024];
    for (int i = tid; i < 1024; i += 256) bf[i] = g_bw[b * R_ * D_ + c * 1024 + i];
    __syncthreads();
    int j = jb * 256 + tid;
    float acc = 0.f;
    #pragma unroll 8
    for (int i = 0; i < 1024; i++)
        acc = fmaf(bf[i], Wp1[(size_t)(c * 1024 + i) * 512 + j], acc);
    g_hidp[(b * 6 + c) * 512 + j] = acc;
}

__global__ void k_p2(const float* __restrict__ bp1, const float* __restrict__ Wp2,
                     const float* __restrict__ bp2) {
    int b = blockIdx.x;
    int tid = threadIdx.x;
    __shared__ float hd[512];
    for (int j = tid; j < 512; j += 256) {
        float a = bp1[j];
        #pragma unroll
        for (int c = 0; c < 6; c++) a += g_hidp[(b * 6 + c) * 512 + j];
        hd[j] = gelu_f(a);
    }
    __syncthreads();
    int d = blockIdx.y * 256 + tid;
    float acc = bp2[d];
    #pragma unroll 8
    for (int j = 0; j < 512; j++)
        acc = fmaf(hd[j], Wp2[(size_t)j * D_ + d], acc);
    g_repr[b * D_ + d] = acc;
}

// ---------------- final residual + RMSNorm ----------------
__global__ __launch_bounds__(256) void k_final(const float* __restrict__ x,
                                               const float* __restrict__ norm_w,
                                               float* __restrict__ out_xs) {
    int row = blockIdx.x;
    int b = row >> 10;
    const float4* xr = (const float4*)(x + (size_t)row * D_);
    const float4* rp = (const float4*)(g_repr + (size_t)b * D_);
    const float4* nw = (const float4*)norm_w;
    float4 v = xr[threadIdx.x];
    float4 r = rp[threadIdx.x];
    v.x = fmaf(0.1f, r.x, v.x); v.y = fmaf(0.1f, r.y, v.y);
    v.z = fmaf(0.1f, r.z, v.z); v.w = fmaf(0.1f, r.w, v.w);
    float ss = v.x * v.x + v.y * v.y + v.z * v.z + v.w * v.w;
    #pragma unroll
    for (int o = 16; o > 0; o >>= 1) ss += __shfl_xor_sync(0xffffffffu, ss, o);
    __shared__ float rs[8];
    if ((threadIdx.x & 31) == 0) rs[threadIdx.x >> 5] = ss;
    __syncthreads();
    float tot = rs[0] + rs[1] + rs[2] + rs[3] + rs[4] + rs[5] + rs[6] + rs[7];
    float scale = rsqrtf(tot * (1.0f / (float)D_) + 1e-6f);
    float4 w = nw[threadIdx.x];
    float4 o;
    o.x = v.x * scale * w.x; o.y = v.y * scale * w.y;
    o.z = v.z * scale * w.z; o.w = v.w * scale * w.w;
    ((float4*)out_xs)[(size_t)row * 256 + threadIdx.x] = o;
}

// ---------------- launch ----------------
extern "C" void kernel_launch(void* const* d_in, const int* in_sizes, int n_in,
                              void* d_out, int out_size) {
    const float* x          = (const float*)d_in[0];
    const float* role_emb   = (const float*)d_in[1];
    const float* Wr1x       = (const float*)d_in[2];
    const float* Wr1r       = (const float*)d_in[3];
    const float* br1        = (const float*)d_in[4];
    const float* Wr2        = (const float*)d_in[5];
    const float* br2        = (const float*)d_in[6];
    const float* schema_emb = (const float*)d_in[7];
    const float* Wf1        = (const float*)d_in[8];
    const float* bf1        = (const float*)d_in[9];
    const float* Wf2        = (const float*)d_in[10];
    const float* bf2        = (const float*)d_in[11];
    const float* Wp1        = (const float*)d_in[12];
    const float* bp1        = (const float*)d_in[13];
    const float* Wp2        = (const float*)d_in[14];
    const float* bp2        = (const float*)d_in[15];
    const float* Wsel1      = (const float*)d_in[16];
    const float* bsel1      = (const float*)d_in[17];
    const float* Wsel2      = (const float*)d_in[18];
    const float* bsel2      = (const float*)d_in[19];
    const float* norm_w     = (const float*)d_in[20];

    float* out      = (float*)d_out;
    float* out_xs   = out;
    float* out_fit  = out + (size_t)B_ * L_ * D_;
    float* out_selw = out_fit + B_ * S_;
    float* out_best = out_selw + B_ * S_;
    float* out_bw   = out_best + B_;

    cudaFuncSetAttribute(k_big, cudaFuncAttributeMaxDynamicSharedMemorySize, SMTOT);

    k_cvt_x<<<M_ * D_ / 2048, 256>>>(x);
    k_cvt_w<<<dim3(SR_, 8, 8), 256>>>(Wr1x);
    k_xm<<<dim3(B_, 32), 128>>>(x);
    k_selhp<<<dim3(B_, 8), 256>>>(Wsel1);
    k_fitp<<<dim3(B_, S_, 2), 256>>>(schema_emb, Wf1);
    k_fitr<<<dim3(B_, S_), 256>>>(bf1, Wf2, bf2);
    k_sel2<<<B_, 256>>>(bsel1, Wsel2, bsel2, out_fit, out_selw, out_best);
    k_rbp<<<dim3(SR_, 8), 256>>>(role_emb, Wr1r);
    k_big<<<dim3(32, 2, SR_), 256, SMTOT>>>(Wr2, br1);
    k_refine<<<dim3(B_, S_), 256>>>(br2);
    k_cw<<<(B_ * R_ * L_) / 256, 256>>>();
    k_bw<<<dim3(B_, 16), 256>>>(x, out_bw);
    k_p1<<<dim3(B_, 2, 6), 256>>>(Wp1);
    k_p2<<<dim3(B_, 4), 256>>>(bp1, Wp2, bp2);
    k_final<<<M_, 256>>>(x, norm_w, out_xs);
}